// round 3
// baseline (speedup 1.0000x reference)
#include <cuda_runtime.h>
#include <math.h>

#define BB 2
#define SS 1024
#define TT (BB*SS)          // 2048 tokens
#define DD 2048
#define HH 16
#define GG 4
#define DKK 128
#define DVV 128
#define NE 8
#define KTOP 2
#define FF 4096
#define MAXROWS (TT*KTOP + NE*128)   // 5120
#define MAXTILES (MAXROWS/128)       // 40

// ---------------- scratch (device globals; no allocs allowed) ----------------
__device__ float g_h[TT*DD];
__device__ float g_q[TT*HH*DKK];
__device__ float g_k[TT*GG*DKK];
__device__ float g_v[TT*GG*DVV];
__device__ float g_attn[TT*HH*DVV];
__device__ float g_x1[TT*DD];
__device__ float g_t[TT*DD];
__device__ float g_mid[(size_t)MAXROWS*FF];
__device__ float g_mid2[(size_t)MAXROWS*DD];
__device__ int   g_count[NE];
__device__ int   g_offset[NE];
__device__ int   g_tile_e[MAXTILES];
__device__ int   g_pair_e[TT*KTOP];
__device__ int   g_pair_pos[TT*KTOP];
__device__ float g_pair_gate[TT*KTOP];
__device__ int   g_row_token[MAXROWS];
__device__ int   g_row_of_pair[TT*KTOP];

__device__ __forceinline__ float warp_sum(float v) {
    #pragma unroll
    for (int o = 16; o > 0; o >>= 1) v += __shfl_down_sync(0xffffffffu, v, o);
    return v;
}

// ---------------- RMSNorm ----------------
__device__ __forceinline__ void rms_core(const float* __restrict__ x,
                                         const float* __restrict__ w,
                                         float* __restrict__ out) {
    int row = blockIdx.x;
    const float4* xr = (const float4*)(x + (size_t)row * DD);
    float4 vals[2];
    float ss = 0.f;
    #pragma unroll
    for (int l = 0; l < 2; l++) {
        float4 v = xr[threadIdx.x + l * 256];
        vals[l] = v;
        ss += v.x*v.x + v.y*v.y + v.z*v.z + v.w*v.w;
    }
    ss = warp_sum(ss);
    __shared__ float red[8];
    if ((threadIdx.x & 31) == 0) red[threadIdx.x >> 5] = ss;
    __syncthreads();
    float tot = 0.f;
    #pragma unroll
    for (int i = 0; i < 8; i++) tot += red[i];
    float inv = rsqrtf(tot / (float)DD + 1e-6f);
    float4* orow = (float4*)(out + (size_t)row * DD);
    const float4* wr = (const float4*)w;
    #pragma unroll
    for (int l = 0; l < 2; l++) {
        int idx = threadIdx.x + l * 256;
        float4 v = vals[l];
        float4 ww = wr[idx];
        float4 r;
        r.x = v.x * inv * ww.x; r.y = v.y * inv * ww.y;
        r.z = v.z * inv * ww.z; r.w = v.w * inv * ww.w;
        orow[idx] = r;
    }
}

__global__ void __launch_bounds__(256) k_rms1(const float* __restrict__ x,
                                              const float* __restrict__ w) {
    rms_core(x, w, g_h);
}
__global__ void __launch_bounds__(256) k_rms2(const float* __restrict__ w) {
    rms_core(g_x1, w, g_t);
}

// ---------------- generic SGEMM core: C[M,N] = A[M,K] @ B[K,N] ----------------
#define BM 128
#define BN 128
#define BKK 16

__device__ __forceinline__ void gemm_core(
    const float* __restrict__ A, const float* __restrict__ Bmat, float* __restrict__ C,
    int Kdim, int lda, int ldb, int ldc,
    bool silu, const float* __restrict__ resid,
    const int* __restrict__ tile_e, long long strideB,
    const int* __restrict__ gather)
{
    __shared__ float As[BKK * BM];
    __shared__ float Bs[BKK * BN];
    const int nt = blockIdx.x, mt = blockIdx.y;
    const float* Bp = Bmat;
    if (tile_e) {
        int e = tile_e[mt];
        if (e < 0) return;
        Bp += (long long)e * strideB;
    }
    const int tid = threadIdx.x;
    const int tx = tid & 15, ty = tid >> 4;
    float acc[8][8];
    #pragma unroll
    for (int i = 0; i < 8; i++)
        #pragma unroll
        for (int j = 0; j < 8; j++) acc[i][j] = 0.f;

    // A tile load mapping: 512 float4s, 2 per thread
    const int arow0 = tid >> 2;            // 0..63
    const int ac = (tid & 3) * 4;          // 0,4,8,12
    int r0g = mt * BM + arow0;
    int r1g = mt * BM + arow0 + 64;
    if (gather) { r0g = gather[r0g]; r1g = gather[r1g]; }
    const float* Arow0 = A + (size_t)r0g * lda + ac;
    const float* Arow1 = A + (size_t)r1g * lda + ac;
    // B tile load mapping
    const int brow0 = tid >> 5;            // 0..7
    const int bc = (tid & 31) * 4;
    const float* Bbase = Bp + (size_t)brow0 * ldb + (size_t)nt * BN + bc;

    const int nk = Kdim / BKK;
    for (int kt = 0; kt < nk; kt++) {
        const int k0 = kt * BKK;
        float4 a0 = *(const float4*)(Arow0 + k0);
        float4 a1 = *(const float4*)(Arow1 + k0);
        float4 b0 = *(const float4*)(Bbase + (size_t)k0 * ldb);
        float4 b1 = *(const float4*)(Bbase + (size_t)(k0 + 8) * ldb);
        __syncthreads();
        As[(ac + 0) * BM + arow0] = a0.x;
        As[(ac + 1) * BM + arow0] = a0.y;
        As[(ac + 2) * BM + arow0] = a0.z;
        As[(ac + 3) * BM + arow0] = a0.w;
        As[(ac + 0) * BM + arow0 + 64] = a1.x;
        As[(ac + 1) * BM + arow0 + 64] = a1.y;
        As[(ac + 2) * BM + arow0 + 64] = a1.z;
        As[(ac + 3) * BM + arow0 + 64] = a1.w;
        *(float4*)&Bs[brow0 * BN + bc] = b0;
        *(float4*)&Bs[(brow0 + 8) * BN + bc] = b1;
        __syncthreads();
        #pragma unroll
        for (int kk = 0; kk < BKK; kk++) {
            float4 av0 = *(const float4*)&As[kk * BM + ty * 8];
            float4 av1 = *(const float4*)&As[kk * BM + ty * 8 + 4];
            float4 bv0 = *(const float4*)&Bs[kk * BN + tx * 8];
            float4 bv1 = *(const float4*)&Bs[kk * BN + tx * 8 + 4];
            float av[8] = {av0.x, av0.y, av0.z, av0.w, av1.x, av1.y, av1.z, av1.w};
            float bv[8] = {bv0.x, bv0.y, bv0.z, bv0.w, bv1.x, bv1.y, bv1.z, bv1.w};
            #pragma unroll
            for (int i = 0; i < 8; i++)
                #pragma unroll
                for (int j = 0; j < 8; j++)
                    acc[i][j] = fmaf(av[i], bv[j], acc[i][j]);
        }
    }
    // epilogue
    #pragma unroll
    for (int i = 0; i < 8; i++) {
        size_t row = (size_t)(mt * BM + ty * 8 + i);
        float* crow = C + row * ldc + (size_t)nt * BN + tx * 8;
        const float* rrow = resid ? (resid + row * ldc + (size_t)nt * BN + tx * 8) : nullptr;
        #pragma unroll
        for (int j4 = 0; j4 < 2; j4++) {
            float4 v;
            float t0 = acc[i][j4*4+0], t1 = acc[i][j4*4+1], t2 = acc[i][j4*4+2], t3 = acc[i][j4*4+3];
            if (silu) {
                t0 = t0 / (1.f + __expf(-t0));
                t1 = t1 / (1.f + __expf(-t1));
                t2 = t2 / (1.f + __expf(-t2));
                t3 = t3 / (1.f + __expf(-t3));
            }
            if (rrow) {
                t0 += rrow[j4*4+0]; t1 += rrow[j4*4+1];
                t2 += rrow[j4*4+2]; t3 += rrow[j4*4+3];
            }
            v.x = t0; v.y = t1; v.z = t2; v.w = t3;
            *(float4*)(crow + j4 * 4) = v;
        }
    }
}

__global__ void __launch_bounds__(256) k_gemm_q(const float* __restrict__ Wq) {
    gemm_core(g_h, Wq, g_q, DD, DD, HH*DKK, HH*DKK, false, nullptr, nullptr, 0, nullptr);
}
__global__ void __launch_bounds__(256) k_gemm_k(const float* __restrict__ Wk) {
    gemm_core(g_h, Wk, g_k, DD, DD, GG*DKK, GG*DKK, false, nullptr, nullptr, 0, nullptr);
}
__global__ void __launch_bounds__(256) k_gemm_v(const float* __restrict__ Wv) {
    gemm_core(g_h, Wv, g_v, DD, DD, GG*DVV, GG*DVV, false, nullptr, nullptr, 0, nullptr);
}
__global__ void __launch_bounds__(256) k_gemm_o(const float* __restrict__ Wo,
                                                const float* __restrict__ xin) {
    gemm_core(g_attn, Wo, g_x1, HH*DVV, HH*DVV, DD, DD, false, xin, nullptr, 0, nullptr);
}
__global__ void __launch_bounds__(256) k_moe1(const float* __restrict__ W1) {
    gemm_core(g_t, W1, g_mid, DD, DD, FF, FF, true, nullptr, g_tile_e,
              (long long)DD * FF, g_row_token);
}
__global__ void __launch_bounds__(256) k_moe2(const float* __restrict__ W2) {
    gemm_core(g_mid, W2, g_mid2, FF, FF, DD, DD, false, nullptr, g_tile_e,
              (long long)FF * DD, nullptr);
}

// ---------------- RoPE ----------------
__device__ __forceinline__ void rope_core(float* __restrict__ base, int heads) {
    int idx = blockIdx.x;                 // token*heads + head
    int tokenpos = (idx / heads) % SS;    // position within sequence
    float* row = base + (size_t)idx * DKK;
    int i = threadIdx.x;                  // 0..63
    float ex = (float)i * (1.0f / 64.0f);
    float invf = expf(-ex * 9.210340371976184f);   // 10000^{-i/64}
    float ang = (float)tokenpos * invf;
    float c, s;
    sincosf(ang, &s, &c);
    float x1 = row[i], x2 = row[i + 64];
    row[i]      = x1 * c - x2 * s;
    row[i + 64] = x1 * s + x2 * c;
}
__global__ void k_rope_q() { rope_core(g_q, HH); }
__global__ void k_rope_k() { rope_core(g_k, GG); }

// ---------------- Flash attention (fp32, 64x64 tiles, online softmax) ----------------
#define ATTN_SMEM_BYTES ((128*65*2 + 64*128 + 64*65 + 64*3) * 4)

__global__ void __launch_bounds__(256) k_attn() {
    extern __shared__ float sm[];
    float* qs   = sm;                 // [d][m] ld 65
    float* ks   = sm + 128 * 65;      // [d][n] ld 65
    float* vs   = ks + 128 * 65;      // [n][d] ld 128
    float* ps   = vs + 64 * 128;      // [m][n] ld 65
    float* mrow = ps + 64 * 65;
    float* lrow = mrow + 64;
    float* arow = lrow + 64;
    const int qt = blockIdx.x, hh = blockIdx.y, b = blockIdx.z;
    const int g = hh >> 2;            // GQA group (rep = 4)
    const int tid = threadIdx.x;
    const int tx = tid & 15, ty = tid >> 4;

    // load Q tile once
    for (int id = tid; id < 64 * 32; id += 256) {
        int m = id >> 5, d4 = (id & 31) << 2;
        const float* src = g_q + (((size_t)((b * SS + qt * 64 + m) * HH + hh)) << 7) + d4;
        float4 v = *(const float4*)src;
        qs[(d4 + 0) * 65 + m] = v.x;
        qs[(d4 + 1) * 65 + m] = v.y;
        qs[(d4 + 2) * 65 + m] = v.z;
        qs[(d4 + 3) * 65 + m] = v.w;
    }
    if (tid < 64) { mrow[tid] = -1e30f; lrow[tid] = 0.f; }

    float o_acc[4][8];
    #pragma unroll
    for (int i = 0; i < 4; i++)
        #pragma unroll
        for (int j = 0; j < 8; j++) o_acc[i][j] = 0.f;

    const float scale = 0.08838834764831845f;  // DK^-0.5

    for (int kt = 0; kt <= qt; kt++) {
        __syncthreads();
        // load K,V tiles
        for (int id = tid; id < 64 * 32; id += 256) {
            int n = id >> 5, d4 = (id & 31) << 2;
            size_t gidx = (((size_t)((b * SS + kt * 64 + n) * GG + g)) << 7) + d4;
            float4 kv = *(const float4*)(g_k + gidx);
            ks[(d4 + 0) * 65 + n] = kv.x;
            ks[(d4 + 1) * 65 + n] = kv.y;
            ks[(d4 + 2) * 65 + n] = kv.z;
            ks[(d4 + 3) * 65 + n] = kv.w;
            float4 vv = *(const float4*)(g_v + gidx);
            *(float4*)(vs + n * 128 + d4) = vv;
        }
        __syncthreads();
        // phase 1: S = Q K^T
        float sc[4][4];
        #pragma unroll
        for (int i = 0; i < 4; i++)
            #pragma unroll
            for (int j = 0; j < 4; j++) sc[i][j] = 0.f;
        #pragma unroll 4
        for (int kk = 0; kk < 128; kk++) {
            float a0 = qs[kk * 65 + ty * 4 + 0];
            float a1 = qs[kk * 65 + ty * 4 + 1];
            float a2 = qs[kk * 65 + ty * 4 + 2];
            float a3 = qs[kk * 65 + ty * 4 + 3];
            float b0 = ks[kk * 65 + tx];
            float b1 = ks[kk * 65 + tx + 16];
            float b2 = ks[kk * 65 + tx + 32];
            float b3 = ks[kk * 65 + tx + 48];
            sc[0][0] = fmaf(a0, b0, sc[0][0]); sc[0][1] = fmaf(a0, b1, sc[0][1]);
            sc[0][2] = fmaf(a0, b2, sc[0][2]); sc[0][3] = fmaf(a0, b3, sc[0][3]);
            sc[1][0] = fmaf(a1, b0, sc[1][0]); sc[1][1] = fmaf(a1, b1, sc[1][1]);
            sc[1][2] = fmaf(a1, b2, sc[1][2]); sc[1][3] = fmaf(a1, b3, sc[1][3]);
            sc[2][0] = fmaf(a2, b0, sc[2][0]); sc[2][1] = fmaf(a2, b1, sc[2][1]);
            sc[2][2] = fmaf(a2, b2, sc[2][2]); sc[2][3] = fmaf(a2, b3, sc[2][3]);
            sc[3][0] = fmaf(a3, b0, sc[3][0]); sc[3][1] = fmaf(a3, b1, sc[3][1]);
            sc[3][2] = fmaf(a3, b2, sc[3][2]); sc[3][3] = fmaf(a3, b3, sc[3][3]);
        }
        // mask + stage to shared
        #pragma unroll
        for (int i = 0; i < 4; i++) {
            int qi = qt * 64 + ty * 4 + i;
            #pragma unroll
            for (int j = 0; j < 4; j++) {
                int key = kt * 64 + tx + 16 * j;
                float v = sc[i][j] * scale;
                if (key > qi) v = -1e30f;
                ps[(ty * 4 + i) * 65 + tx + 16 * j] = v;
            }
        }
        __syncthreads();
        // online softmax per row
        if (tid < 64) {
            int m = tid;
            float mx = mrow[m];
            float tmax = -1e30f;
            for (int n = 0; n < 64; n++) tmax = fmaxf(tmax, ps[m * 65 + n]);
            float nm = fmaxf(mx, tmax);
            float al = __expf(mx - nm);
            float sum = 0.f;
            for (int n = 0; n < 64; n++) {
                float p = __expf(ps[m * 65 + n] - nm);
                ps[m * 65 + n] = p;
                sum += p;
            }
            lrow[m] = lrow[m] * al + sum;
            mrow[m] = nm;
            arow[m] = al;
        }
        __syncthreads();
        // phase 2: O = alpha*O + P V
        float al[4];
        #pragma unroll
        for (int i = 0; i < 4; i++) al[i] = arow[ty * 4 + i];
        #pragma unroll
        for (int i = 0; i < 4; i++)
            #pragma unroll
            for (int j = 0; j < 8; j++) o_acc[i][j] *= al[i];
        #pragma unroll 2
        for (int n = 0; n < 64; n++) {
            float p0 = ps[(ty * 4 + 0) * 65 + n];
            float p1 = ps[(ty * 4 + 1) * 65 + n];
            float p2 = ps[(ty * 4 + 2) * 65 + n];
            float p3 = ps[(ty * 4 + 3) * 65 + n];
            #pragma unroll
            for (int j = 0; j < 8; j++) {
                float vv = vs[n * 128 + tx + 16 * j];
                o_acc[0][j] = fmaf(p0, vv, o_acc[0][j]);
                o_acc[1][j] = fmaf(p1, vv, o_acc[1][j]);
                o_acc[2][j] = fmaf(p2, vv, o_acc[2][j]);
                o_acc[3][j] = fmaf(p3, vv, o_acc[3][j]);
            }
        }
    }
    // write out
    #pragma unroll
    for (int i = 0; i < 4; i++) {
        float inv = 1.f / lrow[ty * 4 + i];
        float* dst = g_attn + (((size_t)((b * SS + qt * 64 + ty * 4 + i) * HH + hh)) << 7);
        #pragma unroll
        for (int j = 0; j < 8; j++) dst[tx + 16 * j] = o_acc[i][j] * inv;
    }
}

// ---------------- router + MoE bookkeeping ----------------
__global__ void k_zero() { if (threadIdx.x < NE) g_count[threadIdx.x] = 0; }

__global__ void __launch_bounds__(128) k_router(const float* __restrict__ Wr) {
    int tok = blockIdx.x;
    const float* tr = g_t + (size_t)tok * DD;
    float acc[8] = {0,0,0,0,0,0,0,0};
    for (int d = threadIdx.x; d < DD; d += 128) {
        float tv = tr[d];
        const float4* wr = (const float4*)(Wr + (size_t)d * 8);
        float4 w0 = wr[0], w1 = wr[1];
        acc[0] = fmaf(tv, w0.x, acc[0]); acc[1] = fmaf(tv, w0.y, acc[1]);
        acc[2] = fmaf(tv, w0.z, acc[2]); acc[3] = fmaf(tv, w0.w, acc[3]);
        acc[4] = fmaf(tv, w1.x, acc[4]); acc[5] = fmaf(tv, w1.y, acc[5]);
        acc[6] = fmaf(tv, w1.z, acc[6]); acc[7] = fmaf(tv, w1.w, acc[7]);
    }
    __shared__ float red[4][8];
    #pragma unroll
    for (int e = 0; e < 8; e++) {
        float v = warp_sum(acc[e]);
        if ((threadIdx.x & 31) == 0) red[threadIdx.x >> 5][e] = v;
    }
    __syncthreads();
    if (threadIdx.x == 0) {
        float lg[8];
        #pragma unroll
        for (int e = 0; e < 8; e++) lg[e] = red[0][e] + red[1][e] + red[2][e] + red[3][e];
        int i0 = 0;
        for (int e = 1; e < 8; e++) if (lg[e] > lg[i0]) i0 = e;
        int i1 = -1;
        for (int e = 0; e < 8; e++) {
            if (e == i0) continue;
            if (i1 < 0 || lg[e] > lg[i1]) i1 = e;
        }
        float e1v = __expf(lg[i1] - lg[i0]);
        float s = 1.f + e1v;
        float gg0 = 1.f / s, gg1 = e1v / s;
        int p0 = atomicAdd(&g_count[i0], 1);
        int p1 = atomicAdd(&g_count[i1], 1);
        g_pair_e[tok*2]   = i0; g_pair_pos[tok*2]   = p0; g_pair_gate[tok*2]   = gg0;
        g_pair_e[tok*2+1] = i1; g_pair_pos[tok*2+1] = p1; g_pair_gate[tok*2+1] = gg1;
    }
}

__global__ void k_finalize() {
    if (threadIdx.x != 0 || blockIdx.x != 0) return;
    int off = 0;
    for (int e = 0; e < NE; e++) {
        g_offset[e] = off;
        int pt = (g_count[e] + 127) / 128;
        for (int ti = 0; ti < pt; ti++) g_tile_e[off / 128 + ti] = e;
        off += pt * 128;
    }
    for (int i = off / 128; i < MAXTILES; i++) g_tile_e[i] = -1;
}

__global__ void k_rows_init() {
    int i = blockIdx.x * 256 + threadIdx.x;
    if (i < MAXROWS) g_row_token[i] = 0;
}

__global__ void k_rows_place() {
    int p = blockIdx.x * 256 + threadIdx.x;
    if (p < TT * KTOP) {
        int e = g_pair_e[p];
        int row = g_offset[e] + g_pair_pos[p];
        g_row_token[row] = p >> 1;
        g_row_of_pair[p] = row;
    }
}

__global__ void __launch_bounds__(256) k_combine(float* __restrict__ out) {
    int tok = blockIdx.x;
    int r0 = g_row_of_pair[tok*2], r1 = g_row_of_pair[tok*2+1];
    float gg0 = g_pair_gate[tok*2], gg1 = g_pair_gate[tok*2+1];
    const float4* a  = (const float4*)(g_x1  + (size_t)tok * DD);
    const float4* m0 = (const float4*)(g_mid2 + (size_t)r0 * DD);
    const float4* m1 = (const float4*)(g_mid2 + (size_t)r1 * DD);
    float4* o4 = (float4*)(out + (size_t)tok * DD);
    for (int i = threadIdx.x; i < DD / 4; i += 256) {
        float4 av = a[i], v0 = m0[i], v1 = m1[i], r;
        r.x = av.x + gg0 * v0.x + gg1 * v1.x;
        r.y = av.y + gg0 * v0.y + gg1 * v1.y;
        r.z = av.z + gg0 * v0.z + gg1 * v1.z;
        r.w = av.w + gg0 * v0.w + gg1 * v1.w;
        o4[i] = r;
    }
}

// ---------------- launch ----------------
extern "C" void kernel_launch(void* const* d_in, const int* in_sizes, int n_in,
                              void* d_out, int out_size) {
    const float* x    = (const float*)d_in[0];
    const float* ln1w = (const float*)d_in[1];
    const float* Wq   = (const float*)d_in[2];
    const float* Wk   = (const float*)d_in[3];
    const float* Wv   = (const float*)d_in[4];
    const float* Wo   = (const float*)d_in[5];
    const float* ln2w = (const float*)d_in[6];
    const float* Wr   = (const float*)d_in[7];
    const float* W1   = (const float*)d_in[8];
    const float* W2   = (const float*)d_in[9];
    float* out = (float*)d_out;
    (void)in_sizes; (void)n_in; (void)out_size;

    k_rms1<<<TT, 256>>>(x, ln1w);
    k_gemm_q<<<dim3(16, 16), 256>>>(Wq);
    k_gemm_k<<<dim3(4, 16), 256>>>(Wk);
    k_gemm_v<<<dim3(4, 16), 256>>>(Wv);
    k_rope_q<<<TT * HH, 64>>>();
    k_rope_k<<<TT * GG, 64>>>();
    cudaFuncSetAttribute(k_attn, cudaFuncAttributeMaxDynamicSharedMemorySize, ATTN_SMEM_BYTES);
    k_attn<<<dim3(16, 16, 2), 256, ATTN_SMEM_BYTES>>>();
    k_gemm_o<<<dim3(16, 16), 256>>>(Wo, x);
    k_rms2<<<TT, 256>>>(ln2w);
    k_zero<<<1, 32>>>();
    k_router<<<TT, 128>>>(Wr);
    k_finalize<<<1, 1>>>();
    k_rows_init<<<(MAXROWS + 255) / 256, 256>>>();
    k_rows_place<<<(TT * KTOP + 255) / 256, 256>>>();
    k_moe1<<<dim3(FF / 128, MAXTILES), 256>>>(W1);
    k_moe2<<<dim3(DD / 128, MAXTILES), 256>>>(W2);
    k_combine<<<TT, 256>>>(out);
}

// round 4
// speedup vs baseline: 1.5761x; 1.5761x over previous
#include <cuda_runtime.h>
#include <math.h>
#include <stdint.h>

#define BB 2
#define SS 1024
#define TT (BB*SS)          // 2048 tokens
#define DD 2048
#define HH 16
#define GG 4
#define DKK 128
#define DVV 128
#define NE 8
#define KTOP 2
#define FF 4096
#define MAXROWS (TT*KTOP + NE*128)   // 5120
#define MAXTILES (MAXROWS/128)       // 40

// ---------------- scratch (device globals; no allocs allowed) ----------------
__device__ float g_h[TT*DD];
__device__ float g_q[TT*HH*DKK];
__device__ float g_k[TT*GG*DKK];
__device__ float g_v[TT*GG*DVV];
__device__ float g_attn[TT*HH*DVV];
__device__ float g_x1[TT*DD];
__device__ float g_t[TT*DD];
__device__ float g_mid[(size_t)MAXROWS*FF];
__device__ float g_mid2[(size_t)MAXROWS*DD];
__device__ int   g_count[NE];
__device__ int   g_offset[NE];
__device__ int   g_tile_e[MAXTILES];
__device__ int   g_pair_e[TT*KTOP];
__device__ int   g_pair_pos[TT*KTOP];
__device__ float g_pair_gate[TT*KTOP];
__device__ int   g_row_token[MAXROWS];
__device__ int   g_row_of_pair[TT*KTOP];

__device__ __forceinline__ float warp_sum(float v) {
    #pragma unroll
    for (int o = 16; o > 0; o >>= 1) v += __shfl_down_sync(0xffffffffu, v, o);
    return v;
}

// ---------------- RMSNorm ----------------
__device__ __forceinline__ void rms_core(const float* __restrict__ x,
                                         const float* __restrict__ w,
                                         float* __restrict__ out) {
    int row = blockIdx.x;
    const float4* xr = (const float4*)(x + (size_t)row * DD);
    float4 vals[2];
    float ss = 0.f;
    #pragma unroll
    for (int l = 0; l < 2; l++) {
        float4 v = xr[threadIdx.x + l * 256];
        vals[l] = v;
        ss += v.x*v.x + v.y*v.y + v.z*v.z + v.w*v.w;
    }
    ss = warp_sum(ss);
    __shared__ float red[8];
    if ((threadIdx.x & 31) == 0) red[threadIdx.x >> 5] = ss;
    __syncthreads();
    float tot = 0.f;
    #pragma unroll
    for (int i = 0; i < 8; i++) tot += red[i];
    float inv = rsqrtf(tot / (float)DD + 1e-6f);
    float4* orow = (float4*)(out + (size_t)row * DD);
    const float4* wr = (const float4*)w;
    #pragma unroll
    for (int l = 0; l < 2; l++) {
        int idx = threadIdx.x + l * 256;
        float4 v = vals[l];
        float4 ww = wr[idx];
        float4 r;
        r.x = v.x * inv * ww.x; r.y = v.y * inv * ww.y;
        r.z = v.z * inv * ww.z; r.w = v.w * inv * ww.w;
        orow[idx] = r;
    }
}

__global__ void __launch_bounds__(256) k_rms1(const float* __restrict__ x,
                                              const float* __restrict__ w) {
    rms_core(x, w, g_h);
}
__global__ void __launch_bounds__(256) k_rms2(const float* __restrict__ w) {
    rms_core(g_x1, w, g_t);
}

// ---------------- tf32 tensor-core GEMM ----------------
// C[M,N] = A[M,K] @ B[K,N], all row-major fp32; inputs rounded to tf32.
// CTA tile 128x256, BK=16, 8 warps, warp tile 64x64 (m16n8k8 frags).

__device__ __forceinline__ float to_tf32(float x) {
    uint32_t u;
    asm("cvt.rna.tf32.f32 %0, %1;" : "=r"(u) : "f"(x));
    return __uint_as_float(u);
}

__device__ __forceinline__ void mma8(float* c, const uint32_t* a, const uint32_t* b) {
    asm volatile(
        "mma.sync.aligned.m16n8k8.row.col.f32.tf32.tf32.f32 "
        "{%0,%1,%2,%3}, {%4,%5,%6,%7}, {%8,%9}, {%0,%1,%2,%3};"
        : "+f"(c[0]), "+f"(c[1]), "+f"(c[2]), "+f"(c[3])
        : "r"(a[0]), "r"(a[1]), "r"(a[2]), "r"(a[3]), "r"(b[0]), "r"(b[1]));
}

#define TBM 128
#define TBN 256
#define TBK 16
#define ALD 136
#define BLD 264

__device__ __forceinline__ void tgemm(
    const float* __restrict__ A, const float* __restrict__ Bmat, float* __restrict__ C,
    int Kdim, int lda, int ldb, int ldc,
    bool dosilu, const float* __restrict__ resid,
    const int* __restrict__ tile_e, long long strideB,
    const int* __restrict__ gather)
{
    __shared__ float As[TBK][ALD];   // element (k,m) at As[k][m ^ (8*(k>>2))]
    __shared__ float Bs[TBK][BLD];   // element (k,n) at Bs[k][n]
    const int nt = blockIdx.x, mt = blockIdx.y;
    const float* Bp = Bmat;
    if (tile_e) {
        int e = tile_e[mt];
        if (e < 0) return;
        Bp += (long long)e * strideB;
    }
    const int tid = threadIdx.x;
    const int lane = tid & 31, warp = tid >> 5;
    const int wm = warp >> 2, wn = warp & 3;       // 2 x 4 warp grid

    float acc[4][8][4];
    #pragma unroll
    for (int f = 0; f < 4; f++)
        #pragma unroll
        for (int nf = 0; nf < 8; nf++)
            #pragma unroll
            for (int i = 0; i < 4; i++) acc[f][nf][i] = 0.f;

    // staging mappings
    int arow[2], ac4[2];
    const float* aptr[2];
    #pragma unroll
    for (int j = 0; j < 2; j++) {
        int g = tid + 256 * j;
        arow[j] = g >> 2;          // 0..127
        ac4[j]  = g & 3;           // 0..3  (k quad)
        int gr = mt * TBM + arow[j];
        if (gather) gr = gather[gr];
        aptr[j] = A + (size_t)gr * lda + ac4[j] * 4;
    }
    int brow[4], bc4[4];
    const float* bptr[4];
    #pragma unroll
    for (int j = 0; j < 4; j++) {
        int g = tid + 256 * j;
        brow[j] = g >> 6;          // 0..15 (k)
        bc4[j]  = g & 63;          // 0..63 (n quad)
        bptr[j] = Bp + (size_t)brow[j] * ldb + nt * TBN + bc4[j] * 4;
    }

    float4 pa[2], pb[4];
    #pragma unroll
    for (int j = 0; j < 2; j++) pa[j] = *(const float4*)(aptr[j]);
    #pragma unroll
    for (int j = 0; j < 4; j++) pb[j] = *(const float4*)(bptr[j]);

    const int nk = Kdim / TBK;
    for (int kt = 0; kt < nk; kt++) {
        __syncthreads();
        // cvt + store staged tile
        #pragma unroll
        for (int j = 0; j < 2; j++) {
            float4 v = pa[j];
            int c4 = ac4[j];
            int swz = arow[j] ^ (c4 << 3);
            As[c4 * 4 + 0][swz] = to_tf32(v.x);
            As[c4 * 4 + 1][swz] = to_tf32(v.y);
            As[c4 * 4 + 2][swz] = to_tf32(v.z);
            As[c4 * 4 + 3][swz] = to_tf32(v.w);
        }
        #pragma unroll
        for (int j = 0; j < 4; j++) {
            float4 v = pb[j];
            v.x = to_tf32(v.x); v.y = to_tf32(v.y);
            v.z = to_tf32(v.z); v.w = to_tf32(v.w);
            *(float4*)&Bs[brow[j]][bc4[j] * 4] = v;
        }
        __syncthreads();
        if (kt + 1 < nk) {
            int koff = (kt + 1) * TBK;
            #pragma unroll
            for (int j = 0; j < 2; j++) pa[j] = *(const float4*)(aptr[j] + koff);
            #pragma unroll
            for (int j = 0; j < 4; j++) pb[j] = *(const float4*)(bptr[j] + (size_t)koff * ldb);
        }
        // compute 2 ksteps of 8
        const int r = lane >> 2, cl = lane & 3;
        #pragma unroll
        for (int s = 0; s < 2; s++) {
            const int k0 = s * 8;
            const int X1 = 16 * s;
            const int X2 = 16 * s + 8;
            uint32_t af[4][4];
            #pragma unroll
            for (int f = 0; f < 4; f++) {
                int m0 = wm * 64 + f * 16 + r;
                af[f][0] = __float_as_uint(As[k0 + cl][(m0) ^ X1]);
                af[f][1] = __float_as_uint(As[k0 + cl][(m0 + 8) ^ X1]);
                af[f][2] = __float_as_uint(As[k0 + cl + 4][(m0) ^ X2]);
                af[f][3] = __float_as_uint(As[k0 + cl + 4][(m0 + 8) ^ X2]);
            }
            uint32_t bf[8][2];
            #pragma unroll
            for (int nf = 0; nf < 8; nf++) {
                int n0 = wn * 64 + nf * 8 + r;
                bf[nf][0] = __float_as_uint(Bs[k0 + cl][n0]);
                bf[nf][1] = __float_as_uint(Bs[k0 + cl + 4][n0]);
            }
            #pragma unroll
            for (int f = 0; f < 4; f++)
                #pragma unroll
                for (int nf = 0; nf < 8; nf++)
                    mma8(acc[f][nf], af[f], bf[nf]);
        }
    }

    // epilogue
    const int r = lane >> 2, cl = lane & 3;
    #pragma unroll
    for (int f = 0; f < 4; f++) {
        #pragma unroll
        for (int h = 0; h < 2; h++) {
            size_t gr = (size_t)(mt * TBM + wm * 64 + f * 16 + r + h * 8);
            float* crow = C + gr * ldc;
            const float* rrow = resid ? (resid + gr * ldc) : nullptr;
            #pragma unroll
            for (int nf = 0; nf < 8; nf++) {
                int gc = nt * TBN + wn * 64 + nf * 8 + cl * 2;
                float v0 = acc[f][nf][h * 2 + 0];
                float v1 = acc[f][nf][h * 2 + 1];
                if (dosilu) {
                    v0 = v0 / (1.f + __expf(-v0));
                    v1 = v1 / (1.f + __expf(-v1));
                }
                if (rrow) { v0 += rrow[gc]; v1 += rrow[gc + 1]; }
                float2 o; o.x = v0; o.y = v1;
                *(float2*)(crow + gc) = o;
            }
        }
    }
}

__global__ void __launch_bounds__(256, 1) k_gemm_q(const float* __restrict__ Wq) {
    tgemm(g_h, Wq, g_q, DD, DD, HH*DKK, HH*DKK, false, nullptr, nullptr, 0, nullptr);
}
__global__ void __launch_bounds__(256, 1) k_gemm_k(const float* __restrict__ Wk) {
    tgemm(g_h, Wk, g_k, DD, DD, GG*DKK, GG*DKK, false, nullptr, nullptr, 0, nullptr);
}
__global__ void __launch_bounds__(256, 1) k_gemm_v(const float* __restrict__ Wv) {
    tgemm(g_h, Wv, g_v, DD, DD, GG*DVV, GG*DVV, false, nullptr, nullptr, 0, nullptr);
}
__global__ void __launch_bounds__(256, 1) k_gemm_o(const float* __restrict__ Wo,
                                                   const float* __restrict__ xin) {
    tgemm(g_attn, Wo, g_x1, HH*DVV, HH*DVV, DD, DD, false, xin, nullptr, 0, nullptr);
}
__global__ void __launch_bounds__(256, 1) k_moe1(const float* __restrict__ W1) {
    tgemm(g_t, W1, g_mid, DD, DD, FF, FF, true, nullptr, g_tile_e,
          (long long)DD * FF, g_row_token);
}
__global__ void __launch_bounds__(256, 1) k_moe2(const float* __restrict__ W2) {
    tgemm(g_mid, W2, g_mid2, FF, FF, DD, DD, false, nullptr, g_tile_e,
          (long long)FF * DD, nullptr);
}

// ---------------- RoPE ----------------
__device__ __forceinline__ void rope_core(float* __restrict__ base, int heads) {
    int idx = blockIdx.x;                 // token*heads + head
    int tokenpos = (idx / heads) % SS;    // position within sequence
    float* row = base + (size_t)idx * DKK;
    int i = threadIdx.x;                  // 0..63
    float ex = (float)i * (1.0f / 64.0f);
    float invf = expf(-ex * 9.210340371976184f);   // 10000^{-i/64}
    float ang = (float)tokenpos * invf;
    float c, s;
    sincosf(ang, &s, &c);
    float x1 = row[i], x2 = row[i + 64];
    row[i]      = x1 * c - x2 * s;
    row[i + 64] = x1 * s + x2 * c;
}
__global__ void k_rope_q() { rope_core(g_q, HH); }
__global__ void k_rope_k() { rope_core(g_k, GG); }

// ---------------- Flash attention (fp32, 64x64 tiles, online softmax) ----------------
#define ATTN_SMEM_BYTES ((128*65*2 + 64*128 + 64*65 + 64*3) * 4)

__global__ void __launch_bounds__(256) k_attn() {
    extern __shared__ float sm[];
    float* qs   = sm;                 // [d][m] ld 65
    float* ks   = sm + 128 * 65;      // [d][n] ld 65
    float* vs   = ks + 128 * 65;      // [n][d] ld 128
    float* ps   = vs + 64 * 128;      // [m][n] ld 65
    float* mrow = ps + 64 * 65;
    float* lrow = mrow + 64;
    float* arow = lrow + 64;
    const int qt = blockIdx.x, hh = blockIdx.y, b = blockIdx.z;
    const int g = hh >> 2;            // GQA group (rep = 4)
    const int tid = threadIdx.x;
    const int tx = tid & 15, ty = tid >> 4;

    // load Q tile once
    for (int id = tid; id < 64 * 32; id += 256) {
        int m = id >> 5, d4 = (id & 31) << 2;
        const float* src = g_q + (((size_t)((b * SS + qt * 64 + m) * HH + hh)) << 7) + d4;
        float4 v = *(const float4*)src;
        qs[(d4 + 0) * 65 + m] = v.x;
        qs[(d4 + 1) * 65 + m] = v.y;
        qs[(d4 + 2) * 65 + m] = v.z;
        qs[(d4 + 3) * 65 + m] = v.w;
    }
    if (tid < 64) { mrow[tid] = -1e30f; lrow[tid] = 0.f; }

    float o_acc[4][8];
    #pragma unroll
    for (int i = 0; i < 4; i++)
        #pragma unroll
        for (int j = 0; j < 8; j++) o_acc[i][j] = 0.f;

    const float scale = 0.08838834764831845f;  // DK^-0.5

    for (int kt = 0; kt <= qt; kt++) {
        __syncthreads();
        // load K,V tiles
        for (int id = tid; id < 64 * 32; id += 256) {
            int n = id >> 5, d4 = (id & 31) << 2;
            size_t gidx = (((size_t)((b * SS + kt * 64 + n) * GG + g)) << 7) + d4;
            float4 kv = *(const float4*)(g_k + gidx);
            ks[(d4 + 0) * 65 + n] = kv.x;
            ks[(d4 + 1) * 65 + n] = kv.y;
            ks[(d4 + 2) * 65 + n] = kv.z;
            ks[(d4 + 3) * 65 + n] = kv.w;
            float4 vv = *(const float4*)(g_v + gidx);
            *(float4*)(vs + n * 128 + d4) = vv;
        }
        __syncthreads();
        // phase 1: S = Q K^T
        float sc[4][4];
        #pragma unroll
        for (int i = 0; i < 4; i++)
            #pragma unroll
            for (int j = 0; j < 4; j++) sc[i][j] = 0.f;
        #pragma unroll 4
        for (int kk = 0; kk < 128; kk++) {
            float a0 = qs[kk * 65 + ty * 4 + 0];
            float a1 = qs[kk * 65 + ty * 4 + 1];
            float a2 = qs[kk * 65 + ty * 4 + 2];
            float a3 = qs[kk * 65 + ty * 4 + 3];
            float b0 = ks[kk * 65 + tx];
            float b1 = ks[kk * 65 + tx + 16];
            float b2 = ks[kk * 65 + tx + 32];
            float b3 = ks[kk * 65 + tx + 48];
            sc[0][0] = fmaf(a0, b0, sc[0][0]); sc[0][1] = fmaf(a0, b1, sc[0][1]);
            sc[0][2] = fmaf(a0, b2, sc[0][2]); sc[0][3] = fmaf(a0, b3, sc[0][3]);
            sc[1][0] = fmaf(a1, b0, sc[1][0]); sc[1][1] = fmaf(a1, b1, sc[1][1]);
            sc[1][2] = fmaf(a1, b2, sc[1][2]); sc[1][3] = fmaf(a1, b3, sc[1][3]);
            sc[2][0] = fmaf(a2, b0, sc[2][0]); sc[2][1] = fmaf(a2, b1, sc[2][1]);
            sc[2][2] = fmaf(a2, b2, sc[2][2]); sc[2][3] = fmaf(a2, b3, sc[2][3]);
            sc[3][0] = fmaf(a3, b0, sc[3][0]); sc[3][1] = fmaf(a3, b1, sc[3][1]);
            sc[3][2] = fmaf(a3, b2, sc[3][2]); sc[3][3] = fmaf(a3, b3, sc[3][3]);
        }
        // mask + stage to shared
        #pragma unroll
        for (int i = 0; i < 4; i++) {
            int qi = qt * 64 + ty * 4 + i;
            #pragma unroll
            for (int j = 0; j < 4; j++) {
                int key = kt * 64 + tx + 16 * j;
                float v = sc[i][j] * scale;
                if (key > qi) v = -1e30f;
                ps[(ty * 4 + i) * 65 + tx + 16 * j] = v;
            }
        }
        __syncthreads();
        // online softmax per row
        if (tid < 64) {
            int m = tid;
            float mx = mrow[m];
            float tmax = -1e30f;
            for (int n = 0; n < 64; n++) tmax = fmaxf(tmax, ps[m * 65 + n]);
            float nm = fmaxf(mx, tmax);
            float al = __expf(mx - nm);
            float sum = 0.f;
            for (int n = 0; n < 64; n++) {
                float p = __expf(ps[m * 65 + n] - nm);
                ps[m * 65 + n] = p;
                sum += p;
            }
            lrow[m] = lrow[m] * al + sum;
            mrow[m] = nm;
            arow[m] = al;
        }
        __syncthreads();
        // phase 2: O = alpha*O + P V
        float al[4];
        #pragma unroll
        for (int i = 0; i < 4; i++) al[i] = arow[ty * 4 + i];
        #pragma unroll
        for (int i = 0; i < 4; i++)
            #pragma unroll
            for (int j = 0; j < 8; j++) o_acc[i][j] *= al[i];
        #pragma unroll 2
        for (int n = 0; n < 64; n++) {
            float p0 = ps[(ty * 4 + 0) * 65 + n];
            float p1 = ps[(ty * 4 + 1) * 65 + n];
            float p2 = ps[(ty * 4 + 2) * 65 + n];
            float p3 = ps[(ty * 4 + 3) * 65 + n];
            #pragma unroll
            for (int j = 0; j < 8; j++) {
                float vv = vs[n * 128 + tx + 16 * j];
                o_acc[0][j] = fmaf(p0, vv, o_acc[0][j]);
                o_acc[1][j] = fmaf(p1, vv, o_acc[1][j]);
                o_acc[2][j] = fmaf(p2, vv, o_acc[2][j]);
                o_acc[3][j] = fmaf(p3, vv, o_acc[3][j]);
            }
        }
    }
    // write out
    #pragma unroll
    for (int i = 0; i < 4; i++) {
        float inv = 1.f / lrow[ty * 4 + i];
        float* dst = g_attn + (((size_t)((b * SS + qt * 64 + ty * 4 + i) * HH + hh)) << 7);
        #pragma unroll
        for (int j = 0; j < 8; j++) dst[tx + 16 * j] = o_acc[i][j] * inv;
    }
}

// ---------------- router + MoE bookkeeping ----------------
__global__ void k_zero() { if (threadIdx.x < NE) g_count[threadIdx.x] = 0; }

__global__ void __launch_bounds__(128) k_router(const float* __restrict__ Wr) {
    int tok = blockIdx.x;
    const float* tr = g_t + (size_t)tok * DD;
    float acc[8] = {0,0,0,0,0,0,0,0};
    for (int d = threadIdx.x; d < DD; d += 128) {
        float tv = tr[d];
        const float4* wr = (const float4*)(Wr + (size_t)d * 8);
        float4 w0 = wr[0], w1 = wr[1];
        acc[0] = fmaf(tv, w0.x, acc[0]); acc[1] = fmaf(tv, w0.y, acc[1]);
        acc[2] = fmaf(tv, w0.z, acc[2]); acc[3] = fmaf(tv, w0.w, acc[3]);
        acc[4] = fmaf(tv, w1.x, acc[4]); acc[5] = fmaf(tv, w1.y, acc[5]);
        acc[6] = fmaf(tv, w1.z, acc[6]); acc[7] = fmaf(tv, w1.w, acc[7]);
    }
    __shared__ float red[4][8];
    #pragma unroll
    for (int e = 0; e < 8; e++) {
        float v = warp_sum(acc[e]);
        if ((threadIdx.x & 31) == 0) red[threadIdx.x >> 5][e] = v;
    }
    __syncthreads();
    if (threadIdx.x == 0) {
        float lg[8];
        #pragma unroll
        for (int e = 0; e < 8; e++) lg[e] = red[0][e] + red[1][e] + red[2][e] + red[3][e];
        int i0 = 0;
        for (int e = 1; e < 8; e++) if (lg[e] > lg[i0]) i0 = e;
        int i1 = -1;
        for (int e = 0; e < 8; e++) {
            if (e == i0) continue;
            if (i1 < 0 || lg[e] > lg[i1]) i1 = e;
        }
        float e1v = __expf(lg[i1] - lg[i0]);
        float s = 1.f + e1v;
        float gg0 = 1.f / s, gg1 = e1v / s;
        int p0 = atomicAdd(&g_count[i0], 1);
        int p1 = atomicAdd(&g_count[i1], 1);
        g_pair_e[tok*2]   = i0; g_pair_pos[tok*2]   = p0; g_pair_gate[tok*2]   = gg0;
        g_pair_e[tok*2+1] = i1; g_pair_pos[tok*2+1] = p1; g_pair_gate[tok*2+1] = gg1;
    }
}

__global__ void k_finalize() {
    if (threadIdx.x != 0 || blockIdx.x != 0) return;
    int off = 0;
    for (int e = 0; e < NE; e++) {
        g_offset[e] = off;
        int pt = (g_count[e] + 127) / 128;
        for (int ti = 0; ti < pt; ti++) g_tile_e[off / 128 + ti] = e;
        off += pt * 128;
    }
    for (int i = off / 128; i < MAXTILES; i++) g_tile_e[i] = -1;
}

__global__ void k_rows_init() {
    int i = blockIdx.x * 256 + threadIdx.x;
    if (i < MAXROWS) g_row_token[i] = 0;
}

__global__ void k_rows_place() {
    int p = blockIdx.x * 256 + threadIdx.x;
    if (p < TT * KTOP) {
        int e = g_pair_e[p];
        int row = g_offset[e] + g_pair_pos[p];
        g_row_token[row] = p >> 1;
        g_row_of_pair[p] = row;
    }
}

__global__ void __launch_bounds__(256) k_combine(float* __restrict__ out) {
    int tok = blockIdx.x;
    int r0 = g_row_of_pair[tok*2], r1 = g_row_of_pair[tok*2+1];
    float gg0 = g_pair_gate[tok*2], gg1 = g_pair_gate[tok*2+1];
    const float4* a  = (const float4*)(g_x1  + (size_t)tok * DD);
    const float4* m0 = (const float4*)(g_mid2 + (size_t)r0 * DD);
    const float4* m1 = (const float4*)(g_mid2 + (size_t)r1 * DD);
    float4* o4 = (float4*)(out + (size_t)tok * DD);
    for (int i = threadIdx.x; i < DD / 4; i += 256) {
        float4 av = a[i], v0 = m0[i], v1 = m1[i], r;
        r.x = av.x + gg0 * v0.x + gg1 * v1.x;
        r.y = av.y + gg0 * v0.y + gg1 * v1.y;
        r.z = av.z + gg0 * v0.z + gg1 * v1.z;
        r.w = av.w + gg0 * v0.w + gg1 * v1.w;
        o4[i] = r;
    }
}

// ---------------- launch ----------------
extern "C" void kernel_launch(void* const* d_in, const int* in_sizes, int n_in,
                              void* d_out, int out_size) {
    const float* x    = (const float*)d_in[0];
    const float* ln1w = (const float*)d_in[1];
    const float* Wq   = (const float*)d_in[2];
    const float* Wk   = (const float*)d_in[3];
    const float* Wv   = (const float*)d_in[4];
    const float* Wo   = (const float*)d_in[5];
    const float* ln2w = (const float*)d_in[6];
    const float* Wr   = (const float*)d_in[7];
    const float* W1   = (const float*)d_in[8];
    const float* W2   = (const float*)d_in[9];
    float* out = (float*)d_out;
    (void)in_sizes; (void)n_in; (void)out_size;

    k_rms1<<<TT, 256>>>(x, ln1w);
    k_gemm_q<<<dim3(HH*DKK/TBN, TT/TBM), 256>>>(Wq);   // (8,16)
    k_gemm_k<<<dim3(GG*DKK/TBN, TT/TBM), 256>>>(Wk);   // (2,16)
    k_gemm_v<<<dim3(GG*DVV/TBN, TT/TBM), 256>>>(Wv);   // (2,16)
    k_rope_q<<<TT * HH, 64>>>();
    k_rope_k<<<TT * GG, 64>>>();
    cudaFuncSetAttribute(k_attn, cudaFuncAttributeMaxDynamicSharedMemorySize, ATTN_SMEM_BYTES);
    k_attn<<<dim3(16, 16, 2), 256, ATTN_SMEM_BYTES>>>();
    k_gemm_o<<<dim3(DD/TBN, TT/TBM), 256>>>(Wo, x);    // (8,16)
    k_rms2<<<TT, 256>>>(ln2w);
    k_zero<<<1, 32>>>();
    k_router<<<TT, 128>>>(Wr);
    k_finalize<<<1, 1>>>();
    k_rows_init<<<(MAXROWS + 255) / 256, 256>>>();
    k_rows_place<<<(TT * KTOP + 255) / 256, 256>>>();
    k_moe1<<<dim3(FF/TBN, MAXTILES), 256>>>(W1);       // (16,40)
    k_moe2<<<dim3(DD/TBN, MAXTILES), 256>>>(W2);       // (8,40)
    k_combine<<<TT, 256>>>(out);
}

// round 5
// speedup vs baseline: 2.8793x; 1.8269x over previous
#include <cuda_runtime.h>
#include <math.h>
#include <stdint.h>

#define BB 2
#define SS 1024
#define TT (BB*SS)          // 2048 tokens
#define DD 2048
#define HH 16
#define GG 4
#define DKK 128
#define DVV 128
#define NE 8
#define KTOP 2
#define FF 4096
#define MAXROWS (TT*KTOP + NE*128)   // 5120
#define MAXTILES (MAXROWS/128)       // 40

// ---------------- scratch (device globals; no allocs allowed) ----------------
__device__ float g_h[TT*DD];
__device__ float g_q[TT*HH*DKK];
__device__ float g_k[TT*GG*DKK];
__device__ float g_v[TT*GG*DVV];
__device__ float g_attn[TT*HH*DVV];
__device__ float g_x1[TT*DD];
__device__ float g_t[TT*DD];
__device__ float g_mid[(size_t)MAXROWS*FF];
__device__ float g_mid2[(size_t)MAXROWS*DD];
__device__ int   g_count[NE];
__device__ int   g_offset[NE];
__device__ int   g_tile_e[MAXTILES];
__device__ int   g_pair_e[TT*KTOP];
__device__ int   g_pair_pos[TT*KTOP];
__device__ float g_pair_gate[TT*KTOP];
__device__ int   g_row_token[MAXROWS];
__device__ int   g_row_of_pair[TT*KTOP];

__device__ __forceinline__ float warp_sum(float v) {
    #pragma unroll
    for (int o = 16; o > 0; o >>= 1) v += __shfl_down_sync(0xffffffffu, v, o);
    return v;
}

// ---------------- RMSNorm ----------------
__device__ __forceinline__ void rms_core(const float* __restrict__ x,
                                         const float* __restrict__ w,
                                         float* __restrict__ out) {
    int row = blockIdx.x;
    const float4* xr = (const float4*)(x + (size_t)row * DD);
    float4 vals[2];
    float ss = 0.f;
    #pragma unroll
    for (int l = 0; l < 2; l++) {
        float4 v = xr[threadIdx.x + l * 256];
        vals[l] = v;
        ss += v.x*v.x + v.y*v.y + v.z*v.z + v.w*v.w;
    }
    ss = warp_sum(ss);
    __shared__ float red[8];
    if ((threadIdx.x & 31) == 0) red[threadIdx.x >> 5] = ss;
    __syncthreads();
    float tot = 0.f;
    #pragma unroll
    for (int i = 0; i < 8; i++) tot += red[i];
    float inv = rsqrtf(tot / (float)DD + 1e-6f);
    float4* orow = (float4*)(out + (size_t)row * DD);
    const float4* wr = (const float4*)w;
    #pragma unroll
    for (int l = 0; l < 2; l++) {
        int idx = threadIdx.x + l * 256;
        float4 v = vals[l];
        float4 ww = wr[idx];
        float4 r;
        r.x = v.x * inv * ww.x; r.y = v.y * inv * ww.y;
        r.z = v.z * inv * ww.z; r.w = v.w * inv * ww.w;
        orow[idx] = r;
    }
}

__global__ void __launch_bounds__(256) k_rms1(const float* __restrict__ x,
                                              const float* __restrict__ w) {
    rms_core(x, w, g_h);
}
__global__ void __launch_bounds__(256) k_rms2(const float* __restrict__ w) {
    rms_core(g_x1, w, g_t);
}

// ---------------- tf32 tensor-core GEMM (2-stage pipeline) ----------------
__device__ __forceinline__ float to_tf32(float x) {
    uint32_t u;
    asm("cvt.rna.tf32.f32 %0, %1;" : "=r"(u) : "f"(x));
    return __uint_as_float(u);
}

__device__ __forceinline__ void mma8(float* c, const uint32_t* a, const uint32_t* b) {
    asm volatile(
        "mma.sync.aligned.m16n8k8.row.col.f32.tf32.tf32.f32 "
        "{%0,%1,%2,%3}, {%4,%5,%6,%7}, {%8,%9}, {%0,%1,%2,%3};"
        : "+f"(c[0]), "+f"(c[1]), "+f"(c[2]), "+f"(c[3])
        : "r"(a[0]), "r"(a[1]), "r"(a[2]), "r"(a[3]), "r"(b[0]), "r"(b[1]));
}

#define TBM 128
#define TBN 256
#define TBK 16
#define ALD 136
#define BLD 264
#define ASTAGE (TBK*ALD)
#define BSTAGE (TBK*BLD)
#define TG_SMEM ((2*(ASTAGE+BSTAGE))*4)   // 51200 bytes

__device__ __forceinline__ void tgemm(
    const float* __restrict__ A, const float* __restrict__ Bmat, float* __restrict__ C,
    int Kdim, int lda, int ldb, int ldc, int nt, int mt,
    bool dosilu, const float* __restrict__ resid,
    const int* __restrict__ gather)
{
    extern __shared__ float sm_g[];
    float* Asm = sm_g;                    // [2][TBK][ALD], (k,m) at [k][m ^ (8*(k>>2))]
    float* Bsm = sm_g + 2 * ASTAGE;       // [2][TBK][BLD], (k,n) at [k][n]
    const int tid = threadIdx.x;
    const int lane = tid & 31, warp = tid >> 5;
    const int wm = warp >> 2, wn = warp & 3;       // 2 x 4 warp grid

    float acc[4][8][4];
    #pragma unroll
    for (int f = 0; f < 4; f++)
        #pragma unroll
        for (int nf = 0; nf < 8; nf++)
            #pragma unroll
            for (int i = 0; i < 4; i++) acc[f][nf][i] = 0.f;

    // staging mappings
    int arow[2], ac4[2];
    const float* aptr[2];
    #pragma unroll
    for (int j = 0; j < 2; j++) {
        int g = tid + 256 * j;
        arow[j] = g >> 2;          // 0..127
        ac4[j]  = g & 3;           // k-quad
        int gr = mt * TBM + arow[j];
        if (gather) gr = gather[gr];
        aptr[j] = A + (size_t)gr * lda + ac4[j] * 4;
    }
    int brow[4], bc4[4];
    const float* bptr[4];
    #pragma unroll
    for (int j = 0; j < 4; j++) {
        int g = tid + 256 * j;
        brow[j] = g >> 6;          // k 0..15
        bc4[j]  = g & 63;          // n-quad
        bptr[j] = Bmat + (size_t)brow[j] * ldb + nt * TBN + bc4[j] * 4;
    }

    float4 pa[2], pb[4];
    #pragma unroll
    for (int j = 0; j < 2; j++) pa[j] = *(const float4*)(aptr[j]);
    #pragma unroll
    for (int j = 0; j < 4; j++) pb[j] = *(const float4*)(bptr[j]);

    // store stage 0
    {
        float* As0 = Asm; float* Bs0 = Bsm;
        #pragma unroll
        for (int j = 0; j < 2; j++) {
            float4 v = pa[j];
            int c4 = ac4[j];
            int swz = arow[j] ^ (c4 << 3);
            As0[(c4 * 4 + 0) * ALD + swz] = to_tf32(v.x);
            As0[(c4 * 4 + 1) * ALD + swz] = to_tf32(v.y);
            As0[(c4 * 4 + 2) * ALD + swz] = to_tf32(v.z);
            As0[(c4 * 4 + 3) * ALD + swz] = to_tf32(v.w);
        }
        #pragma unroll
        for (int j = 0; j < 4; j++) {
            float4 v = pb[j];
            v.x = to_tf32(v.x); v.y = to_tf32(v.y);
            v.z = to_tf32(v.z); v.w = to_tf32(v.w);
            *(float4*)&Bs0[brow[j] * BLD + bc4[j] * 4] = v;
        }
    }
    __syncthreads();

    const int nk = Kdim / TBK;
    const int r = lane >> 2, cl = lane & 3;
    for (int kt = 0; kt < nk; kt++) {
        if (kt + 1 < nk) {
            int koff = (kt + 1) * TBK;
            #pragma unroll
            for (int j = 0; j < 2; j++) pa[j] = *(const float4*)(aptr[j] + koff);
            #pragma unroll
            for (int j = 0; j < 4; j++) pb[j] = *(const float4*)(bptr[j] + (size_t)koff * ldb);
        }
        // compute current stage
        {
            const float* As = Asm + (kt & 1) * ASTAGE;
            const float* Bs = Bsm + (kt & 1) * BSTAGE;
            #pragma unroll
            for (int s = 0; s < 2; s++) {
                const int k0 = s * 8;
                const int X1 = 16 * s;
                const int X2 = 16 * s + 8;
                uint32_t af[4][4];
                #pragma unroll
                for (int f = 0; f < 4; f++) {
                    int m0 = wm * 64 + f * 16 + r;
                    af[f][0] = __float_as_uint(As[(k0 + cl) * ALD + ((m0) ^ X1)]);
                    af[f][1] = __float_as_uint(As[(k0 + cl) * ALD + ((m0 + 8) ^ X1)]);
                    af[f][2] = __float_as_uint(As[(k0 + cl + 4) * ALD + ((m0) ^ X2)]);
                    af[f][3] = __float_as_uint(As[(k0 + cl + 4) * ALD + ((m0 + 8) ^ X2)]);
                }
                uint32_t bf[8][2];
                #pragma unroll
                for (int nf = 0; nf < 8; nf++) {
                    int n0 = wn * 64 + nf * 8 + r;
                    bf[nf][0] = __float_as_uint(Bs[(k0 + cl) * BLD + n0]);
                    bf[nf][1] = __float_as_uint(Bs[(k0 + cl + 4) * BLD + n0]);
                }
                #pragma unroll
                for (int f = 0; f < 4; f++)
                    #pragma unroll
                    for (int nf = 0; nf < 8; nf++)
                        mma8(acc[f][nf], af[f], bf[nf]);
            }
        }
        // store next stage
        if (kt + 1 < nk) {
            float* As = Asm + ((kt + 1) & 1) * ASTAGE;
            float* Bs = Bsm + ((kt + 1) & 1) * BSTAGE;
            #pragma unroll
            for (int j = 0; j < 2; j++) {
                float4 v = pa[j];
                int c4 = ac4[j];
                int swz = arow[j] ^ (c4 << 3);
                As[(c4 * 4 + 0) * ALD + swz] = to_tf32(v.x);
                As[(c4 * 4 + 1) * ALD + swz] = to_tf32(v.y);
                As[(c4 * 4 + 2) * ALD + swz] = to_tf32(v.z);
                As[(c4 * 4 + 3) * ALD + swz] = to_tf32(v.w);
            }
            #pragma unroll
            for (int j = 0; j < 4; j++) {
                float4 v = pb[j];
                v.x = to_tf32(v.x); v.y = to_tf32(v.y);
                v.z = to_tf32(v.z); v.w = to_tf32(v.w);
                *(float4*)&Bs[brow[j] * BLD + bc4[j] * 4] = v;
            }
        }
        __syncthreads();
    }

    // epilogue
    #pragma unroll
    for (int f = 0; f < 4; f++) {
        #pragma unroll
        for (int h = 0; h < 2; h++) {
            size_t gr = (size_t)(mt * TBM + wm * 64 + f * 16 + r + h * 8);
            float* crow = C + gr * ldc;
            const float* rrow = resid ? (resid + gr * ldc) : nullptr;
            #pragma unroll
            for (int nf = 0; nf < 8; nf++) {
                int gc = nt * TBN + wn * 64 + nf * 8 + cl * 2;
                float v0 = acc[f][nf][h * 2 + 0];
                float v1 = acc[f][nf][h * 2 + 1];
                if (dosilu) {
                    v0 = v0 / (1.f + __expf(-v0));
                    v1 = v1 / (1.f + __expf(-v1));
                }
                if (rrow) { v0 += rrow[gc]; v1 += rrow[gc + 1]; }
                float2 o; o.x = v0; o.y = v1;
                *(float2*)(crow + gc) = o;
            }
        }
    }
}

// fused QKV: N-tiles 0..7 -> Wq, 8..9 -> Wk, 10..11 -> Wv
__global__ void __launch_bounds__(256, 1) k_gemm_qkv(const float* __restrict__ Wq,
                                                     const float* __restrict__ Wk,
                                                     const float* __restrict__ Wv) {
    int nt = blockIdx.x, mt = blockIdx.y;
    const float* Bp; float* Cp; int ld;
    if (nt < 8)       { Bp = Wq; Cp = g_q; ld = HH * DKK; }
    else if (nt < 10) { Bp = Wk; Cp = g_k; ld = GG * DKK; nt -= 8; }
    else              { Bp = Wv; Cp = g_v; ld = GG * DVV; nt -= 10; }
    tgemm(g_h, Bp, Cp, DD, DD, ld, ld, nt, mt, false, nullptr, nullptr);
}
__global__ void __launch_bounds__(256, 1) k_gemm_o(const float* __restrict__ Wo,
                                                   const float* __restrict__ xin) {
    tgemm(g_attn, Wo, g_x1, HH*DVV, HH*DVV, DD, DD, blockIdx.x, blockIdx.y,
          false, xin, nullptr);
}
__global__ void __launch_bounds__(256, 1) k_moe1(const float* __restrict__ W1) {
    int e = g_tile_e[blockIdx.y];
    if (e < 0) return;
    tgemm(g_t, W1 + (long long)e * DD * FF, g_mid, DD, DD, FF, FF,
          blockIdx.x, blockIdx.y, true, nullptr, g_row_token);
}
__global__ void __launch_bounds__(256, 1) k_moe2(const float* __restrict__ W2) {
    int e = g_tile_e[blockIdx.y];
    if (e < 0) return;
    tgemm(g_mid, W2 + (long long)e * FF * DD, g_mid2, FF, FF, DD, DD,
          blockIdx.x, blockIdx.y, false, nullptr, nullptr);
}

// ---------------- RoPE ----------------
__device__ __forceinline__ void rope_core(float* __restrict__ base, int heads) {
    int idx = blockIdx.x;
    int tokenpos = (idx / heads) % SS;
    float* row = base + (size_t)idx * DKK;
    int i = threadIdx.x;                  // 0..63
    float ex = (float)i * (1.0f / 64.0f);
    float invf = expf(-ex * 9.210340371976184f);
    float ang = (float)tokenpos * invf;
    float c, s;
    sincosf(ang, &s, &c);
    float x1 = row[i], x2 = row[i + 64];
    row[i]      = x1 * c - x2 * s;
    row[i + 64] = x1 * s + x2 * c;
}
__global__ void k_rope_q() { rope_core(g_q, HH); }
__global__ void k_rope_k() { rope_core(g_k, GG); }

// ---------------- Flash attention, tf32 MMA ----------------
// 64 q-rows x 64 kv per tile; 8 warps.
// S phase: warp grid 4(m) x 2(n): warp tile 16x32.
// PV phase: warp grid 4(m) x 2(d): warp tile 16x64.
#define QLD 132
#define PLD 68
#define ATTN_SMEM ((3*64*QLD + 64*PLD + 3*64) * 4)   // 119552 B

__global__ void __launch_bounds__(256) k_attn() {
    extern __shared__ float sm_a[];
    float* qs   = sm_a;                 // [m][k] ld 132
    float* ks   = qs + 64 * QLD;        // [n][k] ld 132
    float* vs   = ks + 64 * QLD;        // [n][d] ld 132
    float* ps   = vs + 64 * QLD;        // [m][n] ld 68
    float* mrow = ps + 64 * PLD;
    float* lrow = mrow + 64;
    float* arow = lrow + 64;
    const int qt = blockIdx.x, hh = blockIdx.y, b = blockIdx.z;
    const int g = hh >> 2;
    const int tid = threadIdx.x;
    const int lane = tid & 31, warp = tid >> 5;
    const int r = lane >> 2, cl = lane & 3;
    const int swm = warp >> 1, swn = warp & 1;
    const int m0 = swm * 16;

    // load Q tile once: rows are (b, qt*64+m, head hh)
    for (int id = tid; id < 64 * 32; id += 256) {
        int m = id >> 5, c4 = (id & 31) << 2;
        const float* src = g_q + (((size_t)((b * SS + qt * 64 + m) * HH + hh)) << 7) + c4;
        *(float4*)&qs[m * QLD + c4] = *(const float4*)src;
    }
    if (tid < 64) { mrow[tid] = -1e30f; lrow[tid] = 0.f; }

    float oacc[8][4];
    #pragma unroll
    for (int nf = 0; nf < 8; nf++)
        #pragma unroll
        for (int i = 0; i < 4; i++) oacc[nf][i] = 0.f;

    const float scale = 0.08838834764831845f;  // DK^-0.5

    for (int kt = 0; kt <= qt; kt++) {
        __syncthreads();   // prev PV done reading ks/vs/ps; Q visible on first iter
        for (int id = tid; id < 64 * 32; id += 256) {
            int n = id >> 5, c4 = (id & 31) << 2;
            size_t gidx = (((size_t)((b * SS + kt * 64 + n) * GG + g)) << 7) + c4;
            *(float4*)&ks[n * QLD + c4] = *(const float4*)(g_k + gidx);
            *(float4*)&vs[n * QLD + c4] = *(const float4*)(g_v + gidx);
        }
        __syncthreads();

        // S = Q K^T  (warp tile 16 x 32, 4 n8 tiles, 16 ksteps)
        float sacc[4][4];
        #pragma unroll
        for (int t = 0; t < 4; t++)
            #pragma unroll
            for (int i = 0; i < 4; i++) sacc[t][i] = 0.f;
        const int sn0 = swn * 32;
        #pragma unroll
        for (int ks8 = 0; ks8 < 16; ks8++) {
            int k0 = ks8 * 8;
            uint32_t a[4];
            a[0] = __float_as_uint(to_tf32(qs[(m0 + r) * QLD + k0 + cl]));
            a[1] = __float_as_uint(to_tf32(qs[(m0 + r + 8) * QLD + k0 + cl]));
            a[2] = __float_as_uint(to_tf32(qs[(m0 + r) * QLD + k0 + cl + 4]));
            a[3] = __float_as_uint(to_tf32(qs[(m0 + r + 8) * QLD + k0 + cl + 4]));
            #pragma unroll
            for (int t = 0; t < 4; t++) {
                uint32_t bfr[2];
                bfr[0] = __float_as_uint(to_tf32(ks[(sn0 + t * 8 + r) * QLD + k0 + cl]));
                bfr[1] = __float_as_uint(to_tf32(ks[(sn0 + t * 8 + r) * QLD + k0 + cl + 4]));
                mma8(sacc[t], a, bfr);
            }
        }
        // scale + causal mask + stage P scores to shared
        {
            int gm0 = qt * 64 + m0 + r;
            #pragma unroll
            for (int t = 0; t < 4; t++) {
                int gn = kt * 64 + sn0 + t * 8 + 2 * cl;
                float v0 = sacc[t][0] * scale; if (gn     > gm0)     v0 = -1e30f;
                float v1 = sacc[t][1] * scale; if (gn + 1 > gm0)     v1 = -1e30f;
                float v2 = sacc[t][2] * scale; if (gn     > gm0 + 8) v2 = -1e30f;
                float v3 = sacc[t][3] * scale; if (gn + 1 > gm0 + 8) v3 = -1e30f;
                float2 p01; p01.x = v0; p01.y = v1;
                float2 p23; p23.x = v2; p23.y = v3;
                *(float2*)&ps[(m0 + r) * PLD + sn0 + t * 8 + 2 * cl] = p01;
                *(float2*)&ps[(m0 + r + 8) * PLD + sn0 + t * 8 + 2 * cl] = p23;
            }
        }
        __syncthreads();
        // online softmax per row
        if (tid < 64) {
            int m = tid;
            float mx = mrow[m];
            float tmax = -1e30f;
            #pragma unroll 8
            for (int n = 0; n < 64; n++) tmax = fmaxf(tmax, ps[m * PLD + n]);
            float nm = fmaxf(mx, tmax);
            float al = __expf(mx - nm);
            float sum = 0.f;
            #pragma unroll 8
            for (int n = 0; n < 64; n++) {
                float p = __expf(ps[m * PLD + n] - nm);
                ps[m * PLD + n] = p;
                sum += p;
            }
            lrow[m] = lrow[m] * al + sum;
            mrow[m] = nm;
            arow[m] = al;
        }
        __syncthreads();
        // PV: O = alpha*O + P V   (warp tile 16 x 64, 8 n8 tiles over d, 8 ksteps)
        {
            float al0 = arow[m0 + r], al1 = arow[m0 + r + 8];
            #pragma unroll
            for (int nf = 0; nf < 8; nf++) {
                oacc[nf][0] *= al0; oacc[nf][1] *= al0;
                oacc[nf][2] *= al1; oacc[nf][3] *= al1;
            }
            const int dn0 = swn * 64;
            #pragma unroll
            for (int ks8 = 0; ks8 < 8; ks8++) {
                int k0 = ks8 * 8;
                uint32_t a[4];
                a[0] = __float_as_uint(to_tf32(ps[(m0 + r) * PLD + k0 + cl]));
                a[1] = __float_as_uint(to_tf32(ps[(m0 + r + 8) * PLD + k0 + cl]));
                a[2] = __float_as_uint(to_tf32(ps[(m0 + r) * PLD + k0 + cl + 4]));
                a[3] = __float_as_uint(to_tf32(ps[(m0 + r + 8) * PLD + k0 + cl + 4]));
                #pragma unroll
                for (int nf = 0; nf < 8; nf++) {
                    uint32_t bfr[2];
                    bfr[0] = __float_as_uint(to_tf32(vs[(k0 + cl) * QLD + dn0 + nf * 8 + r]));
                    bfr[1] = __float_as_uint(to_tf32(vs[(k0 + cl + 4) * QLD + dn0 + nf * 8 + r]));
                    mma8(oacc[nf], a, bfr);
                }
            }
        }
    }
    // write out (rows m0+r and m0+r+8, cols dn0 + nf*8 + 2cl)
    {
        float inv0 = 1.f / lrow[m0 + r];
        float inv1 = 1.f / lrow[m0 + r + 8];
        const int dn0 = swn * 64;
        float* dst0 = g_attn + (((size_t)((b * SS + qt * 64 + m0 + r) * HH + hh)) << 7);
        float* dst1 = g_attn + (((size_t)((b * SS + qt * 64 + m0 + r + 8) * HH + hh)) << 7);
        #pragma unroll
        for (int nf = 0; nf < 8; nf++) {
            int d = dn0 + nf * 8 + 2 * cl;
            float2 o0; o0.x = oacc[nf][0] * inv0; o0.y = oacc[nf][1] * inv0;
            float2 o1; o1.x = oacc[nf][2] * inv1; o1.y = oacc[nf][3] * inv1;
            *(float2*)(dst0 + d) = o0;
            *(float2*)(dst1 + d) = o1;
        }
    }
}

// ---------------- router + MoE bookkeeping ----------------
__global__ void k_zero() { if (threadIdx.x < NE) g_count[threadIdx.x] = 0; }

__global__ void __launch_bounds__(128) k_router(const float* __restrict__ Wr) {
    int tok = blockIdx.x;
    const float* tr = g_t + (size_t)tok * DD;
    float acc[8] = {0,0,0,0,0,0,0,0};
    for (int d = threadIdx.x; d < DD; d += 128) {
        float tv = tr[d];
        const float4* wr = (const float4*)(Wr + (size_t)d * 8);
        float4 w0 = wr[0], w1 = wr[1];
        acc[0] = fmaf(tv, w0.x, acc[0]); acc[1] = fmaf(tv, w0.y, acc[1]);
        acc[2] = fmaf(tv, w0.z, acc[2]); acc[3] = fmaf(tv, w0.w, acc[3]);
        acc[4] = fmaf(tv, w1.x, acc[4]); acc[5] = fmaf(tv, w1.y, acc[5]);
        acc[6] = fmaf(tv, w1.z, acc[6]); acc[7] = fmaf(tv, w1.w, acc[7]);
    }
    __shared__ float red[4][8];
    #pragma unroll
    for (int e = 0; e < 8; e++) {
        float v = warp_sum(acc[e]);
        if ((threadIdx.x & 31) == 0) red[threadIdx.x >> 5][e] = v;
    }
    __syncthreads();
    if (threadIdx.x == 0) {
        float lg[8];
        #pragma unroll
        for (int e = 0; e < 8; e++) lg[e] = red[0][e] + red[1][e] + red[2][e] + red[3][e];
        int i0 = 0;
        for (int e = 1; e < 8; e++) if (lg[e] > lg[i0]) i0 = e;
        int i1 = -1;
        for (int e = 0; e < 8; e++) {
            if (e == i0) continue;
            if (i1 < 0 || lg[e] > lg[i1]) i1 = e;
        }
        float e1v = __expf(lg[i1] - lg[i0]);
        float s = 1.f + e1v;
        float gg0 = 1.f / s, gg1 = e1v / s;
        int p0 = atomicAdd(&g_count[i0], 1);
        int p1 = atomicAdd(&g_count[i1], 1);
        g_pair_e[tok*2]   = i0; g_pair_pos[tok*2]   = p0; g_pair_gate[tok*2]   = gg0;
        g_pair_e[tok*2+1] = i1; g_pair_pos[tok*2+1] = p1; g_pair_gate[tok*2+1] = gg1;
    }
}

__global__ void k_finalize() {
    if (threadIdx.x != 0 || blockIdx.x != 0) return;
    int off = 0;
    for (int e = 0; e < NE; e++) {
        g_offset[e] = off;
        int pt = (g_count[e] + 127) / 128;
        for (int ti = 0; ti < pt; ti++) g_tile_e[off / 128 + ti] = e;
        off += pt * 128;
    }
    for (int i = off / 128; i < MAXTILES; i++) g_tile_e[i] = -1;
}

__global__ void k_rows_init() {
    int i = blockIdx.x * 256 + threadIdx.x;
    if (i < MAXROWS) g_row_token[i] = 0;
}

__global__ void k_rows_place() {
    int p = blockIdx.x * 256 + threadIdx.x;
    if (p < TT * KTOP) {
        int e = g_pair_e[p];
        int row = g_offset[e] + g_pair_pos[p];
        g_row_token[row] = p >> 1;
        g_row_of_pair[p] = row;
    }
}

__global__ void __launch_bounds__(256) k_combine(float* __restrict__ out) {
    int tok = blockIdx.x;
    int r0 = g_row_of_pair[tok*2], r1 = g_row_of_pair[tok*2+1];
    float gg0 = g_pair_gate[tok*2], gg1 = g_pair_gate[tok*2+1];
    const float4* a  = (const float4*)(g_x1  + (size_t)tok * DD);
    const float4* m0 = (const float4*)(g_mid2 + (size_t)r0 * DD);
    const float4* m1 = (const float4*)(g_mid2 + (size_t)r1 * DD);
    float4* o4 = (float4*)(out + (size_t)tok * DD);
    for (int i = threadIdx.x; i < DD / 4; i += 256) {
        float4 av = a[i], v0 = m0[i], v1 = m1[i], r;
        r.x = av.x + gg0 * v0.x + gg1 * v1.x;
        r.y = av.y + gg0 * v0.y + gg1 * v1.y;
        r.z = av.z + gg0 * v0.z + gg1 * v1.z;
        r.w = av.w + gg0 * v0.w + gg1 * v1.w;
        o4[i] = r;
    }
}

// ---------------- launch ----------------
extern "C" void kernel_launch(void* const* d_in, const int* in_sizes, int n_in,
                              void* d_out, int out_size) {
    const float* x    = (const float*)d_in[0];
    const float* ln1w = (const float*)d_in[1];
    const float* Wq   = (const float*)d_in[2];
    const float* Wk   = (const float*)d_in[3];
    const float* Wv   = (const float*)d_in[4];
    const float* Wo   = (const float*)d_in[5];
    const float* ln2w = (const float*)d_in[6];
    const float* Wr   = (const float*)d_in[7];
    const float* W1   = (const float*)d_in[8];
    const float* W2   = (const float*)d_in[9];
    float* out = (float*)d_out;
    (void)in_sizes; (void)n_in; (void)out_size;

    cudaFuncSetAttribute(k_gemm_qkv, cudaFuncAttributeMaxDynamicSharedMemorySize, TG_SMEM);
    cudaFuncSetAttribute(k_gemm_o,   cudaFuncAttributeMaxDynamicSharedMemorySize, TG_SMEM);
    cudaFuncSetAttribute(k_moe1,     cudaFuncAttributeMaxDynamicSharedMemorySize, TG_SMEM);
    cudaFuncSetAttribute(k_moe2,     cudaFuncAttributeMaxDynamicSharedMemorySize, TG_SMEM);
    cudaFuncSetAttribute(k_attn,     cudaFuncAttributeMaxDynamicSharedMemorySize, ATTN_SMEM);

    k_rms1<<<TT, 256>>>(x, ln1w);
    k_gemm_qkv<<<dim3(12, TT/TBM), 256, TG_SMEM>>>(Wq, Wk, Wv);   // 192 CTAs
    k_rope_q<<<TT * HH, 64>>>();
    k_rope_k<<<TT * GG, 64>>>();
    k_attn<<<dim3(16, 16, 2), 256, ATTN_SMEM>>>();
    k_gemm_o<<<dim3(DD/TBN, TT/TBM), 256, TG_SMEM>>>(Wo, x);
    k_rms2<<<TT, 256>>>(ln2w);
    k_zero<<<1, 32>>>();
    k_router<<<TT, 128>>>(Wr);
    k_finalize<<<1, 1>>>();
    k_rows_init<<<(MAXROWS + 255) / 256, 256>>>();
    k_rows_place<<<(TT * KTOP + 255) / 256, 256>>>();
    k_moe1<<<dim3(FF/TBN, MAXTILES), 256, TG_SMEM>>>(W1);
    k_moe2<<<dim3(DD/TBN, MAXTILES), 256, TG_SMEM>>>(W2);
    k_combine<<<TT, 256>>>(out);
}

// round 7
// speedup vs baseline: 5.0262x; 1.7456x over previous
#include <cuda_runtime.h>
#include <cuda_fp16.h>
#include <math.h>
#include <stdint.h>

#define BB 2
#define SS 1024
#define TT (BB*SS)          // 2048 tokens
#define DD 2048
#define HH 16
#define GG 4
#define DKK 128
#define DVV 128
#define NE 8
#define KTOP 2
#define FF 4096
#define MAXROWS (TT*KTOP + NE*128)   // 5120
#define MAXTILES (MAXROWS/128)       // 40

// ---------------- scratch (device globals; no allocs allowed) ----------------
__device__ float g_h[TT*DD];
__device__ float g_q[TT*HH*DKK];
__device__ float g_k[TT*GG*DKK];
__device__ float g_v[TT*GG*DVV];
__device__ float g_attn[TT*HH*DVV];
__device__ float g_x1[TT*DD];
__device__ float g_t[TT*DD];
__device__ float g_mid[(size_t)MAXROWS*FF];
__device__ float g_mid2[(size_t)MAXROWS*DD];
__device__ int   g_count[NE];
__device__ int   g_offset[NE];
__device__ int   g_tile_e[MAXTILES];
__device__ int   g_pair_e[TT*KTOP];
__device__ int   g_pair_pos[TT*KTOP];
__device__ float g_pair_gate[TT*KTOP];
__device__ int   g_row_token[MAXROWS];
__device__ int   g_row_of_pair[TT*KTOP];

__device__ __forceinline__ float warp_sum(float v) {
    #pragma unroll
    for (int o = 16; o > 0; o >>= 1) v += __shfl_down_sync(0xffffffffu, v, o);
    return v;
}

__device__ __forceinline__ uint32_t smem_to_u32(const void* p) {
    uint32_t a;
    asm("{ .reg .u64 t; cvta.to.shared.u64 t, %1; cvt.u32.u64 %0, t; }"
        : "=r"(a) : "l"(p));
    return a;
}

__device__ __forceinline__ uint32_t pack2(float x, float y) {
    __half2 h = __floats2half2_rn(x, y);
    return *reinterpret_cast<uint32_t*>(&h);
}

__device__ __forceinline__ void ldsm_x4(uint32_t* r, uint32_t addr) {
    asm volatile("ldmatrix.sync.aligned.m8n8.x4.shared.b16 {%0,%1,%2,%3}, [%4];"
        : "=r"(r[0]), "=r"(r[1]), "=r"(r[2]), "=r"(r[3]) : "r"(addr));
}
__device__ __forceinline__ void ldsm_x4_t(uint32_t* r, uint32_t addr) {
    asm volatile("ldmatrix.sync.aligned.m8n8.x4.trans.shared.b16 {%0,%1,%2,%3}, [%4];"
        : "=r"(r[0]), "=r"(r[1]), "=r"(r[2]), "=r"(r[3]) : "r"(addr));
}
__device__ __forceinline__ void mma16816(float* c, const uint32_t* a,
                                         uint32_t b0, uint32_t b1) {
    asm volatile(
        "mma.sync.aligned.m16n8k16.row.col.f32.f16.f16.f32 "
        "{%0,%1,%2,%3}, {%4,%5,%6,%7}, {%8,%9}, {%0,%1,%2,%3};"
        : "+f"(c[0]), "+f"(c[1]), "+f"(c[2]), "+f"(c[3])
        : "r"(a[0]), "r"(a[1]), "r"(a[2]), "r"(a[3]), "r"(b0), "r"(b1));
}

// ---------------- RMSNorm ----------------
__device__ __forceinline__ void rms_core(const float* __restrict__ x,
                                         const float* __restrict__ w,
                                         float* __restrict__ out) {
    int row = blockIdx.x;
    const float4* xr = (const float4*)(x + (size_t)row * DD);
    float4 vals[2];
    float ss = 0.f;
    #pragma unroll
    for (int l = 0; l < 2; l++) {
        float4 v = xr[threadIdx.x + l * 256];
        vals[l] = v;
        ss += v.x*v.x + v.y*v.y + v.z*v.z + v.w*v.w;
    }
    ss = warp_sum(ss);
    __shared__ float red[8];
    if ((threadIdx.x & 31) == 0) red[threadIdx.x >> 5] = ss;
    __syncthreads();
    float tot = 0.f;
    #pragma unroll
    for (int i = 0; i < 8; i++) tot += red[i];
    float inv = rsqrtf(tot / (float)DD + 1e-6f);
    float4* orow = (float4*)(out + (size_t)row * DD);
    const float4* wr = (const float4*)w;
    #pragma unroll
    for (int l = 0; l < 2; l++) {
        int idx = threadIdx.x + l * 256;
        float4 v = vals[l];
        float4 ww = wr[idx];
        float4 r;
        r.x = v.x * inv * ww.x; r.y = v.y * inv * ww.y;
        r.z = v.z * inv * ww.z; r.w = v.w * inv * ww.w;
        orow[idx] = r;
    }
}

__global__ void __launch_bounds__(256) k_rms1(const float* __restrict__ x,
                                              const float* __restrict__ w) {
    rms_core(x, w, g_h);
}
__global__ void __launch_bounds__(256) k_rms2(const float* __restrict__ w) {
    rms_core(g_x1, w, g_t);
}

// ---------------- fp16 HMMA GEMM ----------------
// C[M,N] = A[M,K] @ B[K,N], fp32 gmem, fp16 staged, fp32 accumulate.
// CTA tile 128 x 256, BK = 32, double-buffered, 8 warps (2x4), warp tile 64x64.
// A smem: element (m,k): (m>>1)*128 + (m&1)*64 + (((k>>3)^((m>>1)&3))<<4) + (k&7)*2
// B smem: element (k,n): k*512 + (((n>>3)^(k&7))<<4) + (n&7)*2

#define TBM 128
#define TBN 256
#define BKH 32
#define ASZ 8192            // 128*32*2
#define BSZ 16384           // 32*256*2
#define TG_SMEM (2*ASZ + 2*BSZ)   // 49152

template<bool SILU, bool RESID, bool GATHER>
__device__ __forceinline__ void tgemm(
    const float* __restrict__ A, const float* __restrict__ Bmat, float* __restrict__ C,
    int Kdim, int lda, int ldb, int ldc, int nt, int mt,
    const float* __restrict__ resid, const int* __restrict__ gather)
{
    extern __shared__ char smh[];
    const uint32_t smem_u = smem_to_u32(smh);
    const int tid = threadIdx.x;
    const int lane = tid & 31, warp = tid >> 5;
    const int wm = warp >> 2, wn = warp & 3;
    const int mlane = ((lane >> 3) & 1) * 8 + (lane & 7);
    const int lhi = lane >> 4;

    float acc[4][8][4];
    #pragma unroll
    for (int f = 0; f < 4; f++)
        #pragma unroll
        for (int nf = 0; nf < 8; nf++)
            #pragma unroll
            for (int i = 0; i < 4; i++) acc[f][nf][i] = 0.f;

    // A staging: 4 float4/thread -> 8B fp16 each
    const float* aptr[4];
    uint32_t aoff[4];
    #pragma unroll
    for (int j = 0; j < 4; j++) {
        int id = tid + 256 * j;
        int row = id >> 3, q = id & 7;            // k = q*4
        int gr = mt * TBM + row;
        if (GATHER) gr = gather[gr];
        aptr[j] = A + (size_t)gr * lda + q * 4;
        aoff[j] = ((row >> 1) << 7) + ((row & 1) << 6)
                + ((((q >> 1) ^ ((row >> 1) & 3))) << 4) + ((q & 1) << 3);
    }
    // B staging: 8 float4/thread (rows k, coalesced in n)
    const float* bptr[8];
    uint32_t boff[8];
    #pragma unroll
    for (int j = 0; j < 8; j++) {
        int id = tid + 256 * j;
        int kr = id >> 6, nq = id & 63;           // n = nq*4
        bptr[j] = Bmat + (size_t)kr * ldb + nt * TBN + nq * 4;
        boff[j] = (kr << 9) + ((((nq >> 1) ^ (kr & 7))) << 4) + ((nq & 1) << 3);
    }

    float4 pa[4], pb[8];
    #pragma unroll
    for (int j = 0; j < 4; j++) pa[j] = *(const float4*)(aptr[j]);
    #pragma unroll
    for (int j = 0; j < 8; j++) pb[j] = *(const float4*)(bptr[j]);
    // store stage 0
    {
        char* As = smh; char* Bs = smh + 2 * ASZ;
        #pragma unroll
        for (int j = 0; j < 4; j++) {
            uint2 w; w.x = pack2(pa[j].x, pa[j].y); w.y = pack2(pa[j].z, pa[j].w);
            *(uint2*)(As + aoff[j]) = w;
        }
        #pragma unroll
        for (int j = 0; j < 8; j++) {
            uint2 w; w.x = pack2(pb[j].x, pb[j].y); w.y = pack2(pb[j].z, pb[j].w);
            *(uint2*)(Bs + boff[j]) = w;
        }
    }
    __syncthreads();

    const int nk = Kdim / BKH;
    for (int c = 0; c < nk; c++) {
        if (c + 1 < nk) {
            int ko = (c + 1) * BKH;
            #pragma unroll
            for (int j = 0; j < 4; j++) pa[j] = *(const float4*)(aptr[j] + ko);
            #pragma unroll
            for (int j = 0; j < 8; j++) pb[j] = *(const float4*)(bptr[j] + (size_t)ko * ldb);
        }
        // compute current stage
        {
            const uint32_t Abase = smem_u + (c & 1) * ASZ;
            const uint32_t Bbase = smem_u + 2 * ASZ + (c & 1) * BSZ;
            #pragma unroll
            for (int s = 0; s < 2; s++) {
                uint32_t af[4][4];
                #pragma unroll
                for (int f = 0; f < 4; f++) {
                    int m = wm * 64 + f * 16 + mlane;
                    int ch = 2 * s + lhi;
                    ldsm_x4(af[f], Abase + ((m >> 1) << 7) + ((m & 1) << 6)
                                   + (((ch ^ ((m >> 1) & 3))) << 4));
                }
                uint32_t bf[4][4];
                #pragma unroll
                for (int g = 0; g < 4; g++) {
                    int kr = s * 16 + mlane;
                    int chn = wn * 8 + g * 2 + lhi;
                    ldsm_x4_t(bf[g], Bbase + (kr << 9) + (((chn ^ (kr & 7))) << 4));
                }
                #pragma unroll
                for (int f = 0; f < 4; f++)
                    #pragma unroll
                    for (int g = 0; g < 4; g++) {
                        mma16816(acc[f][g*2+0], af[f], bf[g][0], bf[g][1]);
                        mma16816(acc[f][g*2+1], af[f], bf[g][2], bf[g][3]);
                    }
            }
        }
        // store next stage
        if (c + 1 < nk) {
            char* As = smh + ((c + 1) & 1) * ASZ;
            char* Bs = smh + 2 * ASZ + ((c + 1) & 1) * BSZ;
            #pragma unroll
            for (int j = 0; j < 4; j++) {
                uint2 w; w.x = pack2(pa[j].x, pa[j].y); w.y = pack2(pa[j].z, pa[j].w);
                *(uint2*)(As + aoff[j]) = w;
            }
            #pragma unroll
            for (int j = 0; j < 8; j++) {
                uint2 w; w.x = pack2(pb[j].x, pb[j].y); w.y = pack2(pb[j].z, pb[j].w);
                *(uint2*)(Bs + boff[j]) = w;
            }
        }
        __syncthreads();
    }

    // epilogue
    const int r = lane >> 2, cl = lane & 3;
    #pragma unroll
    for (int f = 0; f < 4; f++) {
        #pragma unroll
        for (int h = 0; h < 2; h++) {
            size_t gr = (size_t)(mt * TBM + wm * 64 + f * 16 + r + h * 8);
            float* crow = C + gr * ldc;
            const float* rrow = RESID ? (resid + gr * ldc) : nullptr;
            #pragma unroll
            for (int nf = 0; nf < 8; nf++) {
                int gc = nt * TBN + wn * 64 + nf * 8 + cl * 2;
                float v0 = acc[f][nf][h * 2 + 0];
                float v1 = acc[f][nf][h * 2 + 1];
                if (SILU) {
                    v0 = v0 / (1.f + __expf(-v0));
                    v1 = v1 / (1.f + __expf(-v1));
                }
                if (RESID) { v0 += rrow[gc]; v1 += rrow[gc + 1]; }
                float2 o; o.x = v0; o.y = v1;
                *(float2*)(crow + gc) = o;
            }
        }
    }
}

// fused QKV: N-tiles 0..7 -> Wq, 8..9 -> Wk, 10..11 -> Wv
__global__ void __launch_bounds__(256, 1) k_gemm_qkv(const float* __restrict__ Wq,
                                                     const float* __restrict__ Wk,
                                                     const float* __restrict__ Wv) {
    int nt = blockIdx.x, mt = blockIdx.y;
    if (nt < 8)
        tgemm<false,false,false>(g_h, Wq, g_q, DD, DD, HH*DKK, HH*DKK, nt, mt,
                                 nullptr, nullptr);
    else if (nt < 10)
        tgemm<false,false,false>(g_h, Wk, g_k, DD, DD, GG*DKK, GG*DKK, nt - 8, mt,
                                 nullptr, nullptr);
    else
        tgemm<false,false,false>(g_h, Wv, g_v, DD, DD, GG*DVV, GG*DVV, nt - 10, mt,
                                 nullptr, nullptr);
}
__global__ void __launch_bounds__(256, 1) k_gemm_o(const float* __restrict__ Wo,
                                                   const float* __restrict__ xin) {
    tgemm<false,true,false>(g_attn, Wo, g_x1, HH*DVV, HH*DVV, DD, DD,
                            blockIdx.x, blockIdx.y, xin, nullptr);
}
__global__ void __launch_bounds__(256, 1) k_moe1(const float* __restrict__ W1) {
    int e = g_tile_e[blockIdx.y];
    if (e < 0) return;
    tgemm<true,false,true>(g_t, W1 + (long long)e * DD * FF, g_mid, DD, DD, FF, FF,
                           blockIdx.x, blockIdx.y, nullptr, g_row_token);
}
__global__ void __launch_bounds__(256, 1) k_moe2(const float* __restrict__ W2) {
    int e = g_tile_e[blockIdx.y];
    if (e < 0) return;
    tgemm<false,false,false>(g_mid, W2 + (long long)e * FF * DD, g_mid2, FF, FF, DD, DD,
                             blockIdx.x, blockIdx.y, nullptr, nullptr);
}

// ---------------- RoPE ----------------
__device__ __forceinline__ void rope_core(float* __restrict__ base, int heads) {
    int idx = blockIdx.x;
    int tokenpos = (idx / heads) % SS;
    float* row = base + (size_t)idx * DKK;
    int i = threadIdx.x;                  // 0..63
    float ex = (float)i * (1.0f / 64.0f);
    float invf = expf(-ex * 9.210340371976184f);
    float ang = (float)tokenpos * invf;
    float c, s;
    sincosf(ang, &s, &c);
    float x1 = row[i], x2 = row[i + 64];
    row[i]      = x1 * c - x2 * s;
    row[i + 64] = x1 * s + x2 * c;
}
__global__ void k_rope_q() { rope_core(g_q, HH); }
__global__ void k_rope_k() { rope_core(g_k, GG); }

// ---------------- Flash attention, tf32 mma.sync (R4, known-good) ----------------
__device__ __forceinline__ float to_tf32(float x) {
    uint32_t u;
    asm("cvt.rna.tf32.f32 %0, %1;" : "=r"(u) : "f"(x));
    return __uint_as_float(u);
}
__device__ __forceinline__ void mma8(float* c, const uint32_t* a, const uint32_t* b) {
    asm volatile(
        "mma.sync.aligned.m16n8k8.row.col.f32.tf32.tf32.f32 "
        "{%0,%1,%2,%3}, {%4,%5,%6,%7}, {%8,%9}, {%0,%1,%2,%3};"
        : "+f"(c[0]), "+f"(c[1]), "+f"(c[2]), "+f"(c[3])
        : "r"(a[0]), "r"(a[1]), "r"(a[2]), "r"(a[3]), "r"(b[0]), "r"(b[1]));
}

#define QLD 132
#define PLD 68
#define ATTN_SMEM ((3*64*QLD + 64*PLD + 3*64) * 4)   // 119552 B

__global__ void __launch_bounds__(256) k_attn() {
    extern __shared__ float sm_a[];
    float* qs   = sm_a;                 // [m][k] ld 132
    float* ks   = qs + 64 * QLD;        // [n][k] ld 132
    float* vs   = ks + 64 * QLD;        // [n][d] ld 132
    float* ps   = vs + 64 * QLD;        // [m][n] ld 68
    float* mrow = ps + 64 * PLD;
    float* lrow = mrow + 64;
    float* arow = lrow + 64;
    const int qt = blockIdx.x, hh = blockIdx.y, b = blockIdx.z;
    const int g = hh >> 2;
    const int tid = threadIdx.x;
    const int lane = tid & 31, warp = tid >> 5;
    const int r = lane >> 2, cl = lane & 3;
    const int swm = warp >> 1, swn = warp & 1;
    const int m0 = swm * 16;

    for (int id = tid; id < 64 * 32; id += 256) {
        int m = id >> 5, c4 = (id & 31) << 2;
        const float* src = g_q + (((size_t)((b * SS + qt * 64 + m) * HH + hh)) << 7) + c4;
        *(float4*)&qs[m * QLD + c4] = *(const float4*)src;
    }
    if (tid < 64) { mrow[tid] = -1e30f; lrow[tid] = 0.f; }

    float oacc[8][4];
    #pragma unroll
    for (int nf = 0; nf < 8; nf++)
        #pragma unroll
        for (int i = 0; i < 4; i++) oacc[nf][i] = 0.f;

    const float scale = 0.08838834764831845f;  // DK^-0.5

    for (int kt = 0; kt <= qt; kt++) {
        __syncthreads();
        for (int id = tid; id < 64 * 32; id += 256) {
            int n = id >> 5, c4 = (id & 31) << 2;
            size_t gidx = (((size_t)((b * SS + kt * 64 + n) * GG + g)) << 7) + c4;
            *(float4*)&ks[n * QLD + c4] = *(const float4*)(g_k + gidx);
            *(float4*)&vs[n * QLD + c4] = *(const float4*)(g_v + gidx);
        }
        __syncthreads();

        float sacc[4][4];
        #pragma unroll
        for (int t = 0; t < 4; t++)
            #pragma unroll
            for (int i = 0; i < 4; i++) sacc[t][i] = 0.f;
        const int sn0 = swn * 32;
        #pragma unroll
        for (int ks8 = 0; ks8 < 16; ks8++) {
            int k0 = ks8 * 8;
            uint32_t a[4];
            a[0] = __float_as_uint(to_tf32(qs[(m0 + r) * QLD + k0 + cl]));
            a[1] = __float_as_uint(to_tf32(qs[(m0 + r + 8) * QLD + k0 + cl]));
            a[2] = __float_as_uint(to_tf32(qs[(m0 + r) * QLD + k0 + cl + 4]));
            a[3] = __float_as_uint(to_tf32(qs[(m0 + r + 8) * QLD + k0 + cl + 4]));
            #pragma unroll
            for (int t = 0; t < 4; t++) {
                uint32_t bfr[2];
                bfr[0] = __float_as_uint(to_tf32(ks[(sn0 + t * 8 + r) * QLD + k0 + cl]));
                bfr[1] = __float_as_uint(to_tf32(ks[(sn0 + t * 8 + r) * QLD + k0 + cl + 4]));
                mma8(sacc[t], a, bfr);
            }
        }
        {
            int gm0 = qt * 64 + m0 + r;
            #pragma unroll
            for (int t = 0; t < 4; t++) {
                int gn = kt * 64 + sn0 + t * 8 + 2 * cl;
                float v0 = sacc[t][0] * scale; if (gn     > gm0)     v0 = -1e30f;
                float v1 = sacc[t][1] * scale; if (gn + 1 > gm0)     v1 = -1e30f;
                float v2 = sacc[t][2] * scale; if (gn     > gm0 + 8) v2 = -1e30f;
                float v3 = sacc[t][3] * scale; if (gn + 1 > gm0 + 8) v3 = -1e30f;
                float2 p01; p01.x = v0; p01.y = v1;
                float2 p23; p23.x = v2; p23.y = v3;
                *(float2*)&ps[(m0 + r) * PLD + sn0 + t * 8 + 2 * cl] = p01;
                *(float2*)&ps[(m0 + r + 8) * PLD + sn0 + t * 8 + 2 * cl] = p23;
            }
        }
        __syncthreads();
        if (tid < 64) {
            int m = tid;
            float mx = mrow[m];
            float tmax = -1e30f;
            #pragma unroll 8
            for (int n = 0; n < 64; n++) tmax = fmaxf(tmax, ps[m * PLD + n]);
            float nm = fmaxf(mx, tmax);
            float al = __expf(mx - nm);
            float sum = 0.f;
            #pragma unroll 8
            for (int n = 0; n < 64; n++) {
                float p = __expf(ps[m * PLD + n] - nm);
                ps[m * PLD + n] = p;
                sum += p;
            }
            lrow[m] = lrow[m] * al + sum;
            mrow[m] = nm;
            arow[m] = al;
        }
        __syncthreads();
        {
            float al0 = arow[m0 + r], al1 = arow[m0 + r + 8];
            #pragma unroll
            for (int nf = 0; nf < 8; nf++) {
                oacc[nf][0] *= al0; oacc[nf][1] *= al0;
                oacc[nf][2] *= al1; oacc[nf][3] *= al1;
            }
            const int dn0 = swn * 64;
            #pragma unroll
            for (int ks8 = 0; ks8 < 8; ks8++) {
                int k0 = ks8 * 8;
                uint32_t a[4];
                a[0] = __float_as_uint(to_tf32(ps[(m0 + r) * PLD + k0 + cl]));
                a[1] = __float_as_uint(to_tf32(ps[(m0 + r + 8) * PLD + k0 + cl]));
                a[2] = __float_as_uint(to_tf32(ps[(m0 + r) * PLD + k0 + cl + 4]));
                a[3] = __float_as_uint(to_tf32(ps[(m0 + r + 8) * PLD + k0 + cl + 4]));
                #pragma unroll
                for (int nf = 0; nf < 8; nf++) {
                    uint32_t bfr[2];
                    bfr[0] = __float_as_uint(to_tf32(vs[(k0 + cl) * QLD + dn0 + nf * 8 + r]));
                    bfr[1] = __float_as_uint(to_tf32(vs[(k0 + cl + 4) * QLD + dn0 + nf * 8 + r]));
                    mma8(oacc[nf], a, bfr);
                }
            }
        }
    }
    {
        float inv0 = 1.f / lrow[m0 + r];
        float inv1 = 1.f / lrow[m0 + r + 8];
        const int dn0 = swn * 64;
        float* dst0 = g_attn + (((size_t)((b * SS + qt * 64 + m0 + r) * HH + hh)) << 7);
        float* dst1 = g_attn + (((size_t)((b * SS + qt * 64 + m0 + r + 8) * HH + hh)) << 7);
        #pragma unroll
        for (int nf = 0; nf < 8; nf++) {
            int d = dn0 + nf * 8 + 2 * cl;
            float2 o0; o0.x = oacc[nf][0] * inv0; o0.y = oacc[nf][1] * inv0;
            float2 o1; o1.x = oacc[nf][2] * inv1; o1.y = oacc[nf][3] * inv1;
            *(float2*)(dst0 + d) = o0;
            *(float2*)(dst1 + d) = o1;
        }
    }
}

// ---------------- router + MoE bookkeeping ----------------
__global__ void k_zero() { if (threadIdx.x < NE) g_count[threadIdx.x] = 0; }

__global__ void __launch_bounds__(128) k_router(const float* __restrict__ Wr) {
    int tok = blockIdx.x;
    const float* tr = g_t + (size_t)tok * DD;
    float acc[8] = {0,0,0,0,0,0,0,0};
    for (int d = threadIdx.x; d < DD; d += 128) {
        float tv = tr[d];
        const float4* wr = (const float4*)(Wr + (size_t)d * 8);
        float4 w0 = wr[0], w1 = wr[1];
        acc[0] = fmaf(tv, w0.x, acc[0]); acc[1] = fmaf(tv, w0.y, acc[1]);
        acc[2] = fmaf(tv, w0.z, acc[2]); acc[3] = fmaf(tv, w0.w, acc[3]);
        acc[4] = fmaf(tv, w1.x, acc[4]); acc[5] = fmaf(tv, w1.y, acc[5]);
        acc[6] = fmaf(tv, w1.z, acc[6]); acc[7] = fmaf(tv, w1.w, acc[7]);
    }
    __shared__ float red[4][8];
    #pragma unroll
    for (int e = 0; e < 8; e++) {
        float v = warp_sum(acc[e]);
        if ((threadIdx.x & 31) == 0) red[threadIdx.x >> 5][e] = v;
    }
    __syncthreads();
    if (threadIdx.x == 0) {
        float lg[8];
        #pragma unroll
        for (int e = 0; e < 8; e++) lg[e] = red[0][e] + red[1][e] + red[2][e] + red[3][e];
        int i0 = 0;
        for (int e = 1; e < 8; e++) if (lg[e] > lg[i0]) i0 = e;
        int i1 = -1;
        for (int e = 0; e < 8; e++) {
            if (e == i0) continue;
            if (i1 < 0 || lg[e] > lg[i1]) i1 = e;
        }
        float e1v = __expf(lg[i1] - lg[i0]);
        float s = 1.f + e1v;
        float gg0 = 1.f / s, gg1 = e1v / s;
        int p0 = atomicAdd(&g_count[i0], 1);
        int p1 = atomicAdd(&g_count[i1], 1);
        g_pair_e[tok*2]   = i0; g_pair_pos[tok*2]   = p0; g_pair_gate[tok*2]   = gg0;
        g_pair_e[tok*2+1] = i1; g_pair_pos[tok*2+1] = p1; g_pair_gate[tok*2+1] = gg1;
    }
}

__global__ void k_finalize() {
    if (threadIdx.x != 0 || blockIdx.x != 0) return;
    int off = 0;
    for (int e = 0; e < NE; e++) {
        g_offset[e] = off;
        int pt = (g_count[e] + 127) / 128;
        for (int ti = 0; ti < pt; ti++) g_tile_e[off / 128 + ti] = e;
        off += pt * 128;
    }
    for (int i = off / 128; i < MAXTILES; i++) g_tile_e[i] = -1;
}

__global__ void k_rows_init() {
    int i = blockIdx.x * 256 + threadIdx.x;
    if (i < MAXROWS) g_row_token[i] = 0;
}

__global__ void k_rows_place() {
    int p = blockIdx.x * 256 + threadIdx.x;
    if (p < TT * KTOP) {
        int e = g_pair_e[p];
        int row = g_offset[e] + g_pair_pos[p];
        g_row_token[row] = p >> 1;
        g_row_of_pair[p] = row;
    }
}

__global__ void __launch_bounds__(256) k_combine(float* __restrict__ out) {
    int tok = blockIdx.x;
    int r0 = g_row_of_pair[tok*2], r1 = g_row_of_pair[tok*2+1];
    float gg0 = g_pair_gate[tok*2], gg1 = g_pair_gate[tok*2+1];
    const float4* a  = (const float4*)(g_x1  + (size_t)tok * DD);
    const float4* m0 = (const float4*)(g_mid2 + (size_t)r0 * DD);
    const float4* m1 = (const float4*)(g_mid2 + (size_t)r1 * DD);
    float4* o4 = (float4*)(out + (size_t)tok * DD);
    for (int i = threadIdx.x; i < DD / 4; i += 256) {
        float4 av = a[i], v0 = m0[i], v1 = m1[i], r;
        r.x = av.x + gg0 * v0.x + gg1 * v1.x;
        r.y = av.y + gg0 * v0.y + gg1 * v1.y;
        r.z = av.z + gg0 * v0.z + gg1 * v1.z;
        r.w = av.w + gg0 * v0.w + gg1 * v1.w;
        o4[i] = r;
    }
}

// ---------------- launch ----------------
extern "C" void kernel_launch(void* const* d_in, const int* in_sizes, int n_in,
                              void* d_out, int out_size) {
    const float* x    = (const float*)d_in[0];
    const float* ln1w = (const float*)d_in[1];
    const float* Wq   = (const float*)d_in[2];
    const float* Wk   = (const float*)d_in[3];
    const float* Wv   = (const float*)d_in[4];
    const float* Wo   = (const float*)d_in[5];
    const float* ln2w = (const float*)d_in[6];
    const float* Wr   = (const float*)d_in[7];
    const float* W1   = (const float*)d_in[8];
    const float* W2   = (const float*)d_in[9];
    float* out = (float*)d_out;
    (void)in_sizes; (void)n_in; (void)out_size;

    cudaFuncSetAttribute(k_gemm_qkv, cudaFuncAttributeMaxDynamicSharedMemorySize, TG_SMEM);
    cudaFuncSetAttribute(k_gemm_o,   cudaFuncAttributeMaxDynamicSharedMemorySize, TG_SMEM);
    cudaFuncSetAttribute(k_moe1,     cudaFuncAttributeMaxDynamicSharedMemorySize, TG_SMEM);
    cudaFuncSetAttribute(k_moe2,     cudaFuncAttributeMaxDynamicSharedMemorySize, TG_SMEM);
    cudaFuncSetAttribute(k_attn,     cudaFuncAttributeMaxDynamicSharedMemorySize, ATTN_SMEM);

    k_rms1<<<TT, 256>>>(x, ln1w);
    k_gemm_qkv<<<dim3(12, TT/TBM), 256, TG_SMEM>>>(Wq, Wk, Wv);   // 192 CTAs
    k_rope_q<<<TT * HH, 64>>>();
    k_rope_k<<<TT * GG, 64>>>();
    k_attn<<<dim3(16, 16, 2), 256, ATTN_SMEM>>>();
    k_gemm_o<<<dim3(DD/TBN, TT/TBM), 256, TG_SMEM>>>(Wo, x);      // 128 CTAs
    k_rms2<<<TT, 256>>>(ln2w);
    k_zero<<<1, 32>>>();
    k_router<<<TT, 128>>>(Wr);
    k_finalize<<<1, 1>>>();
    k_rows_init<<<(MAXROWS + 255) / 256, 256>>>();
    k_rows_place<<<(TT * KTOP + 255) / 256, 256>>>();
    k_moe1<<<dim3(FF/TBN, MAXTILES), 256, TG_SMEM>>>(W1);         // (16,40)
    k_moe2<<<dim3(DD/TBN, MAXTILES), 256, TG_SMEM>>>(W2);         // (8,40)
    k_combine<<<TT, 256>>>(out);
}

// round 8
// speedup vs baseline: 5.6003x; 1.1142x over previous
#include <cuda_runtime.h>
#include <cuda_fp16.h>
#include <math.h>
#include <stdint.h>

#define BB 2
#define SS 1024
#define TT (BB*SS)          // 2048 tokens
#define DD 2048
#define HH 16
#define GG 4
#define DKK 128
#define DVV 128
#define NE 8
#define KTOP 2
#define FF 4096
#define MAXROWS (TT*KTOP + NE*128)   // 5120
#define MAXTILES (MAXROWS/128)       // 40

// ---------------- scratch (device globals; no allocs allowed) ----------------
__device__ float g_h[TT*DD];
__device__ float g_q[TT*HH*DKK];
__device__ float g_k[TT*GG*DKK];
__device__ float g_v[TT*GG*DVV];
__device__ float g_attn[TT*HH*DVV];
__device__ float g_x1[TT*DD];
__device__ float g_t[TT*DD];
__device__ float g_mid[(size_t)MAXROWS*FF];
__device__ float g_mid2[(size_t)MAXROWS*DD];
__device__ int   g_count[NE];
__device__ int   g_offset[NE];
__device__ int   g_tile_e[MAXTILES];
__device__ int   g_pair_e[TT*KTOP];
__device__ int   g_pair_pos[TT*KTOP];
__device__ float g_pair_gate[TT*KTOP];
__device__ int   g_row_token[MAXROWS];
__device__ int   g_row_of_pair[TT*KTOP];

__device__ __forceinline__ float warp_sum(float v) {
    #pragma unroll
    for (int o = 16; o > 0; o >>= 1) v += __shfl_down_sync(0xffffffffu, v, o);
    return v;
}

__device__ __forceinline__ uint32_t smem_to_u32(const void* p) {
    uint32_t a;
    asm("{ .reg .u64 t; cvta.to.shared.u64 t, %1; cvt.u32.u64 %0, t; }"
        : "=r"(a) : "l"(p));
    return a;
}

__device__ __forceinline__ uint32_t pack2(float x, float y) {
    __half2 h = __floats2half2_rn(x, y);
    return *reinterpret_cast<uint32_t*>(&h);
}

__device__ __forceinline__ void ldsm_x4(uint32_t* r, uint32_t addr) {
    asm volatile("ldmatrix.sync.aligned.m8n8.x4.shared.b16 {%0,%1,%2,%3}, [%4];"
        : "=r"(r[0]), "=r"(r[1]), "=r"(r[2]), "=r"(r[3]) : "r"(addr));
}
__device__ __forceinline__ void ldsm_x4_t(uint32_t* r, uint32_t addr) {
    asm volatile("ldmatrix.sync.aligned.m8n8.x4.trans.shared.b16 {%0,%1,%2,%3}, [%4];"
        : "=r"(r[0]), "=r"(r[1]), "=r"(r[2]), "=r"(r[3]) : "r"(addr));
}
__device__ __forceinline__ void mma16816(float* c, const uint32_t* a,
                                         uint32_t b0, uint32_t b1) {
    asm volatile(
        "mma.sync.aligned.m16n8k16.row.col.f32.f16.f16.f32 "
        "{%0,%1,%2,%3}, {%4,%5,%6,%7}, {%8,%9}, {%0,%1,%2,%3};"
        : "+f"(c[0]), "+f"(c[1]), "+f"(c[2]), "+f"(c[3])
        : "r"(a[0]), "r"(a[1]), "r"(a[2]), "r"(a[3]), "r"(b0), "r"(b1));
}

// ---------------- RMSNorm ----------------
__device__ __forceinline__ void rms_core(const float* __restrict__ x,
                                         const float* __restrict__ w,
                                         float* __restrict__ out) {
    int row = blockIdx.x;
    const float4* xr = (const float4*)(x + (size_t)row * DD);
    float4 vals[2];
    float ss = 0.f;
    #pragma unroll
    for (int l = 0; l < 2; l++) {
        float4 v = xr[threadIdx.x + l * 256];
        vals[l] = v;
        ss += v.x*v.x + v.y*v.y + v.z*v.z + v.w*v.w;
    }
    ss = warp_sum(ss);
    __shared__ float red[8];
    if ((threadIdx.x & 31) == 0) red[threadIdx.x >> 5] = ss;
    __syncthreads();
    float tot = 0.f;
    #pragma unroll
    for (int i = 0; i < 8; i++) tot += red[i];
    float inv = rsqrtf(tot / (float)DD + 1e-6f);
    float4* orow = (float4*)(out + (size_t)row * DD);
    const float4* wr = (const float4*)w;
    #pragma unroll
    for (int l = 0; l < 2; l++) {
        int idx = threadIdx.x + l * 256;
        float4 v = vals[l];
        float4 ww = wr[idx];
        float4 r;
        r.x = v.x * inv * ww.x; r.y = v.y * inv * ww.y;
        r.z = v.z * inv * ww.z; r.w = v.w * inv * ww.w;
        orow[idx] = r;
    }
}

__global__ void __launch_bounds__(256) k_rms1(const float* __restrict__ x,
                                              const float* __restrict__ w) {
    rms_core(x, w, g_h);
}
__global__ void __launch_bounds__(256) k_rms2(const float* __restrict__ w) {
    rms_core(g_x1, w, g_t);
}

// ---------------- fp16 HMMA GEMM (R6, known-good) ----------------
#define TBM 128
#define TBN 256
#define BKH 32
#define ASZ 8192            // 128*32*2
#define BSZ 16384           // 32*256*2
#define TG_SMEM (2*ASZ + 2*BSZ)   // 49152

template<bool SILU, bool RESID, bool GATHER>
__device__ __forceinline__ void tgemm(
    const float* __restrict__ A, const float* __restrict__ Bmat, float* __restrict__ C,
    int Kdim, int lda, int ldb, int ldc, int nt, int mt,
    const float* __restrict__ resid, const int* __restrict__ gather)
{
    extern __shared__ char smh[];
    const uint32_t smem_u = smem_to_u32(smh);
    const int tid = threadIdx.x;
    const int lane = tid & 31, warp = tid >> 5;
    const int wm = warp >> 2, wn = warp & 3;
    const int mlane = ((lane >> 3) & 1) * 8 + (lane & 7);
    const int lhi = lane >> 4;

    float acc[4][8][4];
    #pragma unroll
    for (int f = 0; f < 4; f++)
        #pragma unroll
        for (int nf = 0; nf < 8; nf++)
            #pragma unroll
            for (int i = 0; i < 4; i++) acc[f][nf][i] = 0.f;

    const float* aptr[4];
    uint32_t aoff[4];
    #pragma unroll
    for (int j = 0; j < 4; j++) {
        int id = tid + 256 * j;
        int row = id >> 3, q = id & 7;
        int gr = mt * TBM + row;
        if (GATHER) gr = gather[gr];
        aptr[j] = A + (size_t)gr * lda + q * 4;
        aoff[j] = ((row >> 1) << 7) + ((row & 1) << 6)
                + ((((q >> 1) ^ ((row >> 1) & 3))) << 4) + ((q & 1) << 3);
    }
    const float* bptr[8];
    uint32_t boff[8];
    #pragma unroll
    for (int j = 0; j < 8; j++) {
        int id = tid + 256 * j;
        int kr = id >> 6, nq = id & 63;
        bptr[j] = Bmat + (size_t)kr * ldb + nt * TBN + nq * 4;
        boff[j] = (kr << 9) + ((((nq >> 1) ^ (kr & 7))) << 4) + ((nq & 1) << 3);
    }

    float4 pa[4], pb[8];
    #pragma unroll
    for (int j = 0; j < 4; j++) pa[j] = *(const float4*)(aptr[j]);
    #pragma unroll
    for (int j = 0; j < 8; j++) pb[j] = *(const float4*)(bptr[j]);
    {
        char* As = smh; char* Bs = smh + 2 * ASZ;
        #pragma unroll
        for (int j = 0; j < 4; j++) {
            uint2 w; w.x = pack2(pa[j].x, pa[j].y); w.y = pack2(pa[j].z, pa[j].w);
            *(uint2*)(As + aoff[j]) = w;
        }
        #pragma unroll
        for (int j = 0; j < 8; j++) {
            uint2 w; w.x = pack2(pb[j].x, pb[j].y); w.y = pack2(pb[j].z, pb[j].w);
            *(uint2*)(Bs + boff[j]) = w;
        }
    }
    __syncthreads();

    const int nk = Kdim / BKH;
    for (int c = 0; c < nk; c++) {
        if (c + 1 < nk) {
            int ko = (c + 1) * BKH;
            #pragma unroll
            for (int j = 0; j < 4; j++) pa[j] = *(const float4*)(aptr[j] + ko);
            #pragma unroll
            for (int j = 0; j < 8; j++) pb[j] = *(const float4*)(bptr[j] + (size_t)ko * ldb);
        }
        {
            const uint32_t Abase = smem_u + (c & 1) * ASZ;
            const uint32_t Bbase = smem_u + 2 * ASZ + (c & 1) * BSZ;
            #pragma unroll
            for (int s = 0; s < 2; s++) {
                uint32_t af[4][4];
                #pragma unroll
                for (int f = 0; f < 4; f++) {
                    int m = wm * 64 + f * 16 + mlane;
                    int ch = 2 * s + lhi;
                    ldsm_x4(af[f], Abase + ((m >> 1) << 7) + ((m & 1) << 6)
                                   + (((ch ^ ((m >> 1) & 3))) << 4));
                }
                uint32_t bf[4][4];
                #pragma unroll
                for (int g = 0; g < 4; g++) {
                    int kr = s * 16 + mlane;
                    int chn = wn * 8 + g * 2 + lhi;
                    ldsm_x4_t(bf[g], Bbase + (kr << 9) + (((chn ^ (kr & 7))) << 4));
                }
                #pragma unroll
                for (int f = 0; f < 4; f++)
                    #pragma unroll
                    for (int g = 0; g < 4; g++) {
                        mma16816(acc[f][g*2+0], af[f], bf[g][0], bf[g][1]);
                        mma16816(acc[f][g*2+1], af[f], bf[g][2], bf[g][3]);
                    }
            }
        }
        if (c + 1 < nk) {
            char* As = smh + ((c + 1) & 1) * ASZ;
            char* Bs = smh + 2 * ASZ + ((c + 1) & 1) * BSZ;
            #pragma unroll
            for (int j = 0; j < 4; j++) {
                uint2 w; w.x = pack2(pa[j].x, pa[j].y); w.y = pack2(pa[j].z, pa[j].w);
                *(uint2*)(As + aoff[j]) = w;
            }
            #pragma unroll
            for (int j = 0; j < 8; j++) {
                uint2 w; w.x = pack2(pb[j].x, pb[j].y); w.y = pack2(pb[j].z, pb[j].w);
                *(uint2*)(Bs + boff[j]) = w;
            }
        }
        __syncthreads();
    }

    const int r = lane >> 2, cl = lane & 3;
    #pragma unroll
    for (int f = 0; f < 4; f++) {
        #pragma unroll
        for (int h = 0; h < 2; h++) {
            size_t gr = (size_t)(mt * TBM + wm * 64 + f * 16 + r + h * 8);
            float* crow = C + gr * ldc;
            const float* rrow = RESID ? (resid + gr * ldc) : nullptr;
            #pragma unroll
            for (int nf = 0; nf < 8; nf++) {
                int gc = nt * TBN + wn * 64 + nf * 8 + cl * 2;
                float v0 = acc[f][nf][h * 2 + 0];
                float v1 = acc[f][nf][h * 2 + 1];
                if (SILU) {
                    v0 = v0 / (1.f + __expf(-v0));
                    v1 = v1 / (1.f + __expf(-v1));
                }
                if (RESID) { v0 += rrow[gc]; v1 += rrow[gc + 1]; }
                float2 o; o.x = v0; o.y = v1;
                *(float2*)(crow + gc) = o;
            }
        }
    }
}

__global__ void __launch_bounds__(256, 1) k_gemm_qkv(const float* __restrict__ Wq,
                                                     const float* __restrict__ Wk,
                                                     const float* __restrict__ Wv) {
    int nt = blockIdx.x, mt = blockIdx.y;
    if (nt < 8)
        tgemm<false,false,false>(g_h, Wq, g_q, DD, DD, HH*DKK, HH*DKK, nt, mt,
                                 nullptr, nullptr);
    else if (nt < 10)
        tgemm<false,false,false>(g_h, Wk, g_k, DD, DD, GG*DKK, GG*DKK, nt - 8, mt,
                                 nullptr, nullptr);
    else
        tgemm<false,false,false>(g_h, Wv, g_v, DD, DD, GG*DVV, GG*DVV, nt - 10, mt,
                                 nullptr, nullptr);
}
__global__ void __launch_bounds__(256, 1) k_gemm_o(const float* __restrict__ Wo,
                                                   const float* __restrict__ xin) {
    tgemm<false,true,false>(g_attn, Wo, g_x1, HH*DVV, HH*DVV, DD, DD,
                            blockIdx.x, blockIdx.y, xin, nullptr);
}
__global__ void __launch_bounds__(256, 1) k_moe1(const float* __restrict__ W1) {
    int e = g_tile_e[blockIdx.y];
    if (e < 0) return;
    tgemm<true,false,true>(g_t, W1 + (long long)e * DD * FF, g_mid, DD, DD, FF, FF,
                           blockIdx.x, blockIdx.y, nullptr, g_row_token);
}
__global__ void __launch_bounds__(256, 1) k_moe2(const float* __restrict__ W2) {
    int e = g_tile_e[blockIdx.y];
    if (e < 0) return;
    tgemm<false,false,false>(g_mid, W2 + (long long)e * FF * DD, g_mid2, FF, FF, DD, DD,
                             blockIdx.x, blockIdx.y, nullptr, nullptr);
}

// ---------------- RoPE ----------------
__device__ __forceinline__ void rope_core(float* __restrict__ base, int heads) {
    int idx = blockIdx.x;
    int tokenpos = (idx / heads) % SS;
    float* row = base + (size_t)idx * DKK;
    int i = threadIdx.x;                  // 0..63
    float ex = (float)i * (1.0f / 64.0f);
    float invf = expf(-ex * 9.210340371976184f);
    float ang = (float)tokenpos * invf;
    float c, s;
    sincosf(ang, &s, &c);
    float x1 = row[i], x2 = row[i + 64];
    row[i]      = x1 * c - x2 * s;
    row[i + 64] = x1 * s + x2 * c;
}
__global__ void k_rope_q() { rope_core(g_q, HH); }
__global__ void k_rope_k() { rope_core(g_k, GG); }

// ---------------- Flash attention, fp16 HMMA + ldmatrix ----------------
// 64 q-rows x 64 kv tiles, 8 warps. S: warps 4(m) x 2(n=32). PV: 4(m) x 2(d=64).
// qs/ks/vs: fp16 [64][136] (272B row). ps: fp32 [64][68]. psh: fp16 [64][72].
#define QROW 272
#define PLD 68
#define PSHROW 144
#define OFF_KS (64*QROW)             // 17408
#define OFF_VS (2*64*QROW)           // 34816
#define OFF_PS (3*64*QROW)           // 52224
#define OFF_PSH (OFF_PS + 64*PLD*4)  // 69632
#define OFF_MISC (OFF_PSH + 64*PSHROW)  // 78848
#define ATTN_SMEM (OFF_MISC + 3*64*4)   // 79616

__global__ void __launch_bounds__(256) k_attn() {
    extern __shared__ char sma[];
    const uint32_t su = smem_to_u32(sma);
    float* ps   = (float*)(sma + OFF_PS);
    float* mrow = (float*)(sma + OFF_MISC);
    float* lrow = mrow + 64;
    float* arow = lrow + 64;
    const int qt = 15 - blockIdx.x;        // longest blocks first
    const int hh = blockIdx.y, b = blockIdx.z;
    const int g = hh >> 2;
    const int tid = threadIdx.x;
    const int lane = tid & 31, warp = tid >> 5;
    const int r = lane >> 2, cl = lane & 3;
    const int mlane = ((lane >> 3) & 1) * 8 + (lane & 7);
    const int lhi = lane >> 4;
    const int swm = warp >> 1, swn = warp & 1;
    const int m0 = swm * 16;

    // load Q tile once (fp32 -> fp16)
    for (int id = tid; id < 64 * 32; id += 256) {
        int m = id >> 5, c4 = (id & 31) << 2;
        const float* src = g_q + (((size_t)((b * SS + qt * 64 + m) * HH + hh)) << 7) + c4;
        float4 v = *(const float4*)src;
        uint2 w; w.x = pack2(v.x, v.y); w.y = pack2(v.z, v.w);
        *(uint2*)(sma + m * QROW + c4 * 2) = w;
    }
    if (tid < 64) { mrow[tid] = -1e30f; lrow[tid] = 0.f; }

    float oacc[8][4];
    #pragma unroll
    for (int nf = 0; nf < 8; nf++)
        #pragma unroll
        for (int i = 0; i < 4; i++) oacc[nf][i] = 0.f;

    const float scale = 0.08838834764831845f;  // DK^-0.5

    for (int kt = 0; kt <= qt; kt++) {
        __syncthreads();
        for (int id = tid; id < 64 * 32; id += 256) {
            int n = id >> 5, c4 = (id & 31) << 2;
            size_t gidx = (((size_t)((b * SS + kt * 64 + n) * GG + g)) << 7) + c4;
            float4 kv = *(const float4*)(g_k + gidx);
            uint2 w; w.x = pack2(kv.x, kv.y); w.y = pack2(kv.z, kv.w);
            *(uint2*)(sma + OFF_KS + n * QROW + c4 * 2) = w;
            float4 vv = *(const float4*)(g_v + gidx);
            uint2 w2; w2.x = pack2(vv.x, vv.y); w2.y = pack2(vv.z, vv.w);
            *(uint2*)(sma + OFF_VS + n * QROW + c4 * 2) = w2;
        }
        __syncthreads();

        // S = Q K^T  (warp tile 16 x 32; 8 k16 steps over dk=128)
        float sacc[4][4];
        #pragma unroll
        for (int t = 0; t < 4; t++)
            #pragma unroll
            for (int i = 0; i < 4; i++) sacc[t][i] = 0.f;
        const int sn0 = swn * 32;
        const uint32_t qb = su + (m0 + mlane) * QROW + lhi * 16;
        const uint32_t kb0 = su + OFF_KS + (sn0 + mlane) * QROW + lhi * 16;
        const uint32_t kb1 = kb0 + 16 * QROW;
        #pragma unroll
        for (int kc = 0; kc < 8; kc++) {
            uint32_t af[4], bk0[4], bk1[4];
            ldsm_x4(af, qb + kc * 32);
            ldsm_x4(bk0, kb0 + kc * 32);
            ldsm_x4(bk1, kb1 + kc * 32);
            mma16816(sacc[0], af, bk0[0], bk0[2]);
            mma16816(sacc[1], af, bk0[1], bk0[3]);
            mma16816(sacc[2], af, bk1[0], bk1[2]);
            mma16816(sacc[3], af, bk1[1], bk1[3]);
        }
        // scale + causal mask + stage scores (fp32)
        {
            int gm0 = qt * 64 + m0 + r;
            #pragma unroll
            for (int t = 0; t < 4; t++) {
                int gn = kt * 64 + sn0 + t * 8 + 2 * cl;
                float v0 = sacc[t][0] * scale; if (gn     > gm0)     v0 = -1e30f;
                float v1 = sacc[t][1] * scale; if (gn + 1 > gm0)     v1 = -1e30f;
                float v2 = sacc[t][2] * scale; if (gn     > gm0 + 8) v2 = -1e30f;
                float v3 = sacc[t][3] * scale; if (gn + 1 > gm0 + 8) v3 = -1e30f;
                float2 p01; p01.x = v0; p01.y = v1;
                float2 p23; p23.x = v2; p23.y = v3;
                *(float2*)&ps[(m0 + r) * PLD + sn0 + t * 8 + 2 * cl] = p01;
                *(float2*)&ps[(m0 + r + 8) * PLD + sn0 + t * 8 + 2 * cl] = p23;
            }
        }
        __syncthreads();
        // online softmax: 4 threads per row, quad shfl reductions; writes P as fp16
        {
            int row = tid >> 2, part = tid & 3;
            float mx = mrow[row];
            const float* pr = ps + row * PLD + part * 16;
            float tmax = -1e30f;
            #pragma unroll
            for (int n = 0; n < 16; n++) tmax = fmaxf(tmax, pr[n]);
            tmax = fmaxf(tmax, __shfl_xor_sync(0xffffffffu, tmax, 1));
            tmax = fmaxf(tmax, __shfl_xor_sync(0xffffffffu, tmax, 2));
            float nm = fmaxf(mx, tmax);
            float al = __expf(mx - nm);
            float sum = 0.f;
            __half* ph = (__half*)(sma + OFF_PSH + row * PSHROW) + part * 16;
            #pragma unroll
            for (int n = 0; n < 16; n += 2) {
                float p0 = __expf(pr[n] - nm);
                float p1 = __expf(pr[n + 1] - nm);
                sum += p0 + p1;
                *(__half2*)(ph + n) = __floats2half2_rn(p0, p1);
            }
            sum += __shfl_xor_sync(0xffffffffu, sum, 1);
            sum += __shfl_xor_sync(0xffffffffu, sum, 2);
            if (part == 0) {
                lrow[row] = lrow[row] * al + sum;
                mrow[row] = nm;
                arow[row] = al;
            }
        }
        __syncthreads();
        // PV: O = alpha*O + P V  (warp tile 16 x 64; 4 k16 steps over kv=64)
        {
            float al0 = arow[m0 + r], al1 = arow[m0 + r + 8];
            #pragma unroll
            for (int nf = 0; nf < 8; nf++) {
                oacc[nf][0] *= al0; oacc[nf][1] *= al0;
                oacc[nf][2] *= al1; oacc[nf][3] *= al1;
            }
            const int dn0 = swn * 64;
            const uint32_t pb = su + OFF_PSH + (m0 + mlane) * PSHROW + lhi * 16;
            const uint32_t vb = su + OFF_VS + mlane * QROW + dn0 * 2 + lhi * 16;
            #pragma unroll
            for (int kc = 0; kc < 4; kc++) {
                uint32_t af[4];
                ldsm_x4(af, pb + kc * 32);
                #pragma unroll
                for (int g2 = 0; g2 < 4; g2++) {
                    uint32_t bf[4];
                    ldsm_x4_t(bf, vb + kc * 16 * QROW + g2 * 32);
                    mma16816(oacc[g2*2+0], af, bf[0], bf[1]);
                    mma16816(oacc[g2*2+1], af, bf[2], bf[3]);
                }
            }
        }
    }
    // write out
    {
        float inv0 = 1.f / lrow[m0 + r];
        float inv1 = 1.f / lrow[m0 + r + 8];
        const int dn0 = swn * 64;
        float* dst0 = g_attn + (((size_t)((b * SS + qt * 64 + m0 + r) * HH + hh)) << 7);
        float* dst1 = g_attn + (((size_t)((b * SS + qt * 64 + m0 + r + 8) * HH + hh)) << 7);
        #pragma unroll
        for (int nf = 0; nf < 8; nf++) {
            int d = dn0 + nf * 8 + 2 * cl;
            float2 o0; o0.x = oacc[nf][0] * inv0; o0.y = oacc[nf][1] * inv0;
            float2 o1; o1.x = oacc[nf][2] * inv1; o1.y = oacc[nf][3] * inv1;
            *(float2*)(dst0 + d) = o0;
            *(float2*)(dst1 + d) = o1;
        }
    }
}

// ---------------- router + MoE bookkeeping ----------------
__global__ void k_zero() { if (threadIdx.x < NE) g_count[threadIdx.x] = 0; }

__global__ void __launch_bounds__(128) k_router(const float* __restrict__ Wr) {
    int tok = blockIdx.x;
    const float* tr = g_t + (size_t)tok * DD;
    float acc[8] = {0,0,0,0,0,0,0,0};
    for (int d = threadIdx.x; d < DD; d += 128) {
        float tv = tr[d];
        const float4* wr = (const float4*)(Wr + (size_t)d * 8);
        float4 w0 = wr[0], w1 = wr[1];
        acc[0] = fmaf(tv, w0.x, acc[0]); acc[1] = fmaf(tv, w0.y, acc[1]);
        acc[2] = fmaf(tv, w0.z, acc[2]); acc[3] = fmaf(tv, w0.w, acc[3]);
        acc[4] = fmaf(tv, w1.x, acc[4]); acc[5] = fmaf(tv, w1.y, acc[5]);
        acc[6] = fmaf(tv, w1.z, acc[6]); acc[7] = fmaf(tv, w1.w, acc[7]);
    }
    __shared__ float red[4][8];
    #pragma unroll
    for (int e = 0; e < 8; e++) {
        float v = warp_sum(acc[e]);
        if ((threadIdx.x & 31) == 0) red[threadIdx.x >> 5][e] = v;
    }
    __syncthreads();
    if (threadIdx.x == 0) {
        float lg[8];
        #pragma unroll
        for (int e = 0; e < 8; e++) lg[e] = red[0][e] + red[1][e] + red[2][e] + red[3][e];
        int i0 = 0;
        for (int e = 1; e < 8; e++) if (lg[e] > lg[i0]) i0 = e;
        int i1 = -1;
        for (int e = 0; e < 8; e++) {
            if (e == i0) continue;
            if (i1 < 0 || lg[e] > lg[i1]) i1 = e;
        }
        float e1v = __expf(lg[i1] - lg[i0]);
        float s = 1.f + e1v;
        float gg0 = 1.f / s, gg1 = e1v / s;
        int p0 = atomicAdd(&g_count[i0], 1);
        int p1 = atomicAdd(&g_count[i1], 1);
        g_pair_e[tok*2]   = i0; g_pair_pos[tok*2]   = p0; g_pair_gate[tok*2]   = gg0;
        g_pair_e[tok*2+1] = i1; g_pair_pos[tok*2+1] = p1; g_pair_gate[tok*2+1] = gg1;
    }
}

__global__ void k_finalize() {
    if (threadIdx.x != 0 || blockIdx.x != 0) return;
    int off = 0;
    for (int e = 0; e < NE; e++) {
        g_offset[e] = off;
        int pt = (g_count[e] + 127) / 128;
        for (int ti = 0; ti < pt; ti++) g_tile_e[off / 128 + ti] = e;
        off += pt * 128;
    }
    for (int i = off / 128; i < MAXTILES; i++) g_tile_e[i] = -1;
}

__global__ void k_rows_init() {
    int i = blockIdx.x * 256 + threadIdx.x;
    if (i < MAXROWS) g_row_token[i] = 0;
}

__global__ void k_rows_place() {
    int p = blockIdx.x * 256 + threadIdx.x;
    if (p < TT * KTOP) {
        int e = g_pair_e[p];
        int row = g_offset[e] + g_pair_pos[p];
        g_row_token[row] = p >> 1;
        g_row_of_pair[p] = row;
    }
}

__global__ void __launch_bounds__(256) k_combine(float* __restrict__ out) {
    int tok = blockIdx.x;
    int r0 = g_row_of_pair[tok*2], r1 = g_row_of_pair[tok*2+1];
    float gg0 = g_pair_gate[tok*2], gg1 = g_pair_gate[tok*2+1];
    const float4* a  = (const float4*)(g_x1  + (size_t)tok * DD);
    const float4* m0 = (const float4*)(g_mid2 + (size_t)r0 * DD);
    const float4* m1 = (const float4*)(g_mid2 + (size_t)r1 * DD);
    float4* o4 = (float4*)(out + (size_t)tok * DD);
    for (int i = threadIdx.x; i < DD / 4; i += 256) {
        float4 av = a[i], v0 = m0[i], v1 = m1[i], r;
        r.x = av.x + gg0 * v0.x + gg1 * v1.x;
        r.y = av.y + gg0 * v0.y + gg1 * v1.y;
        r.z = av.z + gg0 * v0.z + gg1 * v1.z;
        r.w = av.w + gg0 * v0.w + gg1 * v1.w;
        o4[i] = r;
    }
}

// ---------------- launch ----------------
extern "C" void kernel_launch(void* const* d_in, const int* in_sizes, int n_in,
                              void* d_out, int out_size) {
    const float* x    = (const float*)d_in[0];
    const float* ln1w = (const float*)d_in[1];
    const float* Wq   = (const float*)d_in[2];
    const float* Wk   = (const float*)d_in[3];
    const float* Wv   = (const float*)d_in[4];
    const float* Wo   = (const float*)d_in[5];
    const float* ln2w = (const float*)d_in[6];
    const float* Wr   = (const float*)d_in[7];
    const float* W1   = (const float*)d_in[8];
    const float* W2   = (const float*)d_in[9];
    float* out = (float*)d_out;
    (void)in_sizes; (void)n_in; (void)out_size;

    cudaFuncSetAttribute(k_gemm_qkv, cudaFuncAttributeMaxDynamicSharedMemorySize, TG_SMEM);
    cudaFuncSetAttribute(k_gemm_o,   cudaFuncAttributeMaxDynamicSharedMemorySize, TG_SMEM);
    cudaFuncSetAttribute(k_moe1,     cudaFuncAttributeMaxDynamicSharedMemorySize, TG_SMEM);
    cudaFuncSetAttribute(k_moe2,     cudaFuncAttributeMaxDynamicSharedMemorySize, TG_SMEM);
    cudaFuncSetAttribute(k_attn,     cudaFuncAttributeMaxDynamicSharedMemorySize, ATTN_SMEM);

    k_rms1<<<TT, 256>>>(x, ln1w);
    k_gemm_qkv<<<dim3(12, TT/TBM), 256, TG_SMEM>>>(Wq, Wk, Wv);   // 192 CTAs
    k_rope_q<<<TT * HH, 64>>>();
    k_rope_k<<<TT * GG, 64>>>();
    k_attn<<<dim3(16, 16, 2), 256, ATTN_SMEM>>>();
    k_gemm_o<<<dim3(DD/TBN, TT/TBM), 256, TG_SMEM>>>(Wo, x);      // 128 CTAs
    k_rms2<<<TT, 256>>>(ln2w);
    k_zero<<<1, 32>>>();
    k_router<<<TT, 128>>>(Wr);
    k_finalize<<<1, 1>>>();
    k_rows_init<<<(MAXROWS + 255) / 256, 256>>>();
    k_rows_place<<<(TT * KTOP + 255) / 256, 256>>>();
    k_moe1<<<dim3(FF/TBN, MAXTILES), 256, TG_SMEM>>>(W1);         // (16,40)
    k_moe2<<<dim3(DD/TBN, MAXTILES), 256, TG_SMEM>>>(W2);         // (8,40)
    k_combine<<<TT, 256>>>(out);
}

// round 9
// speedup vs baseline: 5.8431x; 1.0434x over previous
#include <cuda_runtime.h>
#include <cuda_fp16.h>
#include <math.h>
#include <stdint.h>

#define BB 2
#define SS 1024
#define TT (BB*SS)          // 2048 tokens
#define DD 2048
#define HH 16
#define GG 4
#define DKK 128
#define DVV 128
#define NE 8
#define KTOP 2
#define FF 4096
#define MAXROWS (TT*KTOP + NE*128)   // 5120
#define MAXTILES (MAXROWS/128)       // 40

// ---------------- scratch (device globals; no allocs allowed) ----------------
__device__ __half g_hh[TT*DD];              // rms1 out (fp16)
__device__ float  g_q[TT*HH*DKK];           // qkv out (fp32, pre-rope)
__device__ float  g_k[TT*GG*DKK];
__device__ __half g_qh[TT*HH*DKK];          // post-rope fp16
__device__ __half g_kh[TT*GG*DKK];
__device__ __half g_vh[TT*GG*DVV];          // qkv V out (fp16 direct)
__device__ __half g_attnh[TT*HH*DVV];       // attention out (fp16)
__device__ float  g_x1[TT*DD];              // residual after attn (fp32)
__device__ float  g_t[TT*DD];               // rms2 out fp32 (router)
__device__ __half g_th[TT*DD];              // rms2 out fp16 (moe1 A)
__device__ __half g_midh[(size_t)MAXROWS*FF];  // moe1 out fp16
__device__ float  g_mid2[(size_t)MAXROWS*DD];  // moe2 out fp32
__device__ int    g_count[NE];
__device__ int    g_offset[NE];
__device__ int    g_tile_e[MAXTILES];
__device__ int    g_pair_e[TT*KTOP];
__device__ int    g_pair_pos[TT*KTOP];
__device__ float  g_pair_gate[TT*KTOP];
__device__ int    g_row_token[MAXROWS];
__device__ int    g_row_of_pair[TT*KTOP];

__device__ __forceinline__ float warp_sum(float v) {
    #pragma unroll
    for (int o = 16; o > 0; o >>= 1) v += __shfl_down_sync(0xffffffffu, v, o);
    return v;
}

__device__ __forceinline__ uint32_t smem_to_u32(const void* p) {
    uint32_t a;
    asm("{ .reg .u64 t; cvta.to.shared.u64 t, %1; cvt.u32.u64 %0, t; }"
        : "=r"(a) : "l"(p));
    return a;
}

__device__ __forceinline__ uint32_t pack2(float x, float y) {
    __half2 h = __floats2half2_rn(x, y);
    return *reinterpret_cast<uint32_t*>(&h);
}

__device__ __forceinline__ void ldsm_x4(uint32_t* r, uint32_t addr) {
    asm volatile("ldmatrix.sync.aligned.m8n8.x4.shared.b16 {%0,%1,%2,%3}, [%4];"
        : "=r"(r[0]), "=r"(r[1]), "=r"(r[2]), "=r"(r[3]) : "r"(addr));
}
__device__ __forceinline__ void ldsm_x4_t(uint32_t* r, uint32_t addr) {
    asm volatile("ldmatrix.sync.aligned.m8n8.x4.trans.shared.b16 {%0,%1,%2,%3}, [%4];"
        : "=r"(r[0]), "=r"(r[1]), "=r"(r[2]), "=r"(r[3]) : "r"(addr));
}
__device__ __forceinline__ void mma16816(float* c, const uint32_t* a,
                                         uint32_t b0, uint32_t b1) {
    asm volatile(
        "mma.sync.aligned.m16n8k16.row.col.f32.f16.f16.f32 "
        "{%0,%1,%2,%3}, {%4,%5,%6,%7}, {%8,%9}, {%0,%1,%2,%3};"
        : "+f"(c[0]), "+f"(c[1]), "+f"(c[2]), "+f"(c[3])
        : "r"(a[0]), "r"(a[1]), "r"(a[2]), "r"(a[3]), "r"(b0), "r"(b1));
}

// ---------------- RMSNorm ----------------
// OUT_F: write fp32 to outf; OUT_H: write fp16 to outh
template<bool OUT_F, bool OUT_H>
__device__ __forceinline__ void rms_core(const float* __restrict__ x,
                                         const float* __restrict__ w,
                                         float* __restrict__ outf,
                                         __half* __restrict__ outh) {
    int row = blockIdx.x;
    const float4* xr = (const float4*)(x + (size_t)row * DD);
    float4 vals[2];
    float ss = 0.f;
    #pragma unroll
    for (int l = 0; l < 2; l++) {
        float4 v = xr[threadIdx.x + l * 256];
        vals[l] = v;
        ss += v.x*v.x + v.y*v.y + v.z*v.z + v.w*v.w;
    }
    ss = warp_sum(ss);
    __shared__ float red[8];
    if ((threadIdx.x & 31) == 0) red[threadIdx.x >> 5] = ss;
    __syncthreads();
    float tot = 0.f;
    #pragma unroll
    for (int i = 0; i < 8; i++) tot += red[i];
    float inv = rsqrtf(tot / (float)DD + 1e-6f);
    const float4* wr = (const float4*)w;
    #pragma unroll
    for (int l = 0; l < 2; l++) {
        int idx = threadIdx.x + l * 256;
        float4 v = vals[l];
        float4 ww = wr[idx];
        float4 r;
        r.x = v.x * inv * ww.x; r.y = v.y * inv * ww.y;
        r.z = v.z * inv * ww.z; r.w = v.w * inv * ww.w;
        if (OUT_F) ((float4*)(outf + (size_t)row * DD))[idx] = r;
        if (OUT_H) {
            uint2 h; h.x = pack2(r.x, r.y); h.y = pack2(r.z, r.w);
            *(uint2*)(outh + (size_t)row * DD + idx * 4) = h;
        }
    }
}

__global__ void __launch_bounds__(256) k_rms1(const float* __restrict__ x,
                                              const float* __restrict__ w) {
    rms_core<false, true>(x, w, nullptr, g_hh);
}
__global__ void __launch_bounds__(256) k_rms2(const float* __restrict__ w) {
    rms_core<true, true>(g_x1, w, g_t, g_th);
}

// ---------------- fp16 HMMA GEMM ----------------
// A: fp16 (AH) global [M,K]; B: fp32 global [K,N] converted in staging;
// C: fp32 or fp16 (OUTH). CTA tile 128x256, BK=32, 2-stage, 8 warps 2x4.
#define TBM 128
#define TBN 256
#define BKH 32
#define ASZ 8192            // 128*32*2
#define BSZ 16384           // 32*256*2
#define TG_SMEM (2*ASZ + 2*BSZ)   // 49152

template<bool SILU, bool RESID, bool GATHER, bool OUTH>
__device__ __forceinline__ void tgemm(
    const __half* __restrict__ A, const float* __restrict__ Bmat, void* __restrict__ Cv,
    int Kdim, int lda, int ldb, int ldc, int nt, int mt,
    const float* __restrict__ resid, const int* __restrict__ gather)
{
    extern __shared__ char smh[];
    const uint32_t smem_u = smem_to_u32(smh);
    const int tid = threadIdx.x;
    const int lane = tid & 31, warp = tid >> 5;
    const int wm = warp >> 2, wn = warp & 3;
    const int mlane = ((lane >> 3) & 1) * 8 + (lane & 7);
    const int lhi = lane >> 4;

    float acc[4][8][4];
    #pragma unroll
    for (int f = 0; f < 4; f++)
        #pragma unroll
        for (int nf = 0; nf < 8; nf++)
            #pragma unroll
            for (int i = 0; i < 4; i++) acc[f][nf][i] = 0.f;

    // A staging: 4 uint2/thread (4 halves each)
    const __half* aptr[4];
    uint32_t aoff[4];
    #pragma unroll
    for (int j = 0; j < 4; j++) {
        int id = tid + 256 * j;
        int row = id >> 3, q = id & 7;
        int gr = mt * TBM + row;
        if (GATHER) gr = gather[gr];
        aptr[j] = A + (size_t)gr * lda + q * 4;
        aoff[j] = ((row >> 1) << 7) + ((row & 1) << 6)
                + ((((q >> 1) ^ ((row >> 1) & 3))) << 4) + ((q & 1) << 3);
    }
    // B staging: 8 float4/thread (fp32 weights, cvt to fp16)
    const float* bptr[8];
    uint32_t boff[8];
    #pragma unroll
    for (int j = 0; j < 8; j++) {
        int id = tid + 256 * j;
        int kr = id >> 6, nq = id & 63;
        bptr[j] = Bmat + (size_t)kr * ldb + nt * TBN + nq * 4;
        boff[j] = (kr << 9) + ((((nq >> 1) ^ (kr & 7))) << 4) + ((nq & 1) << 3);
    }

    uint2 pa[4];
    float4 pb[8];
    #pragma unroll
    for (int j = 0; j < 4; j++) pa[j] = *(const uint2*)(aptr[j]);
    #pragma unroll
    for (int j = 0; j < 8; j++) pb[j] = *(const float4*)(bptr[j]);
    {
        char* As = smh; char* Bs = smh + 2 * ASZ;
        #pragma unroll
        for (int j = 0; j < 4; j++) *(uint2*)(As + aoff[j]) = pa[j];
        #pragma unroll
        for (int j = 0; j < 8; j++) {
            uint2 w; w.x = pack2(pb[j].x, pb[j].y); w.y = pack2(pb[j].z, pb[j].w);
            *(uint2*)(Bs + boff[j]) = w;
        }
    }
    __syncthreads();

    const int nk = Kdim / BKH;
    for (int c = 0; c < nk; c++) {
        if (c + 1 < nk) {
            int ko = (c + 1) * BKH;
            #pragma unroll
            for (int j = 0; j < 4; j++) pa[j] = *(const uint2*)(aptr[j] + ko);
            #pragma unroll
            for (int j = 0; j < 8; j++) pb[j] = *(const float4*)(bptr[j] + (size_t)ko * ldb);
        }
        {
            const uint32_t Abase = smem_u + (c & 1) * ASZ;
            const uint32_t Bbase = smem_u + 2 * ASZ + (c & 1) * BSZ;
            #pragma unroll
            for (int s = 0; s < 2; s++) {
                uint32_t af[4][4];
                #pragma unroll
                for (int f = 0; f < 4; f++) {
                    int m = wm * 64 + f * 16 + mlane;
                    int ch = 2 * s + lhi;
                    ldsm_x4(af[f], Abase + ((m >> 1) << 7) + ((m & 1) << 6)
                                   + (((ch ^ ((m >> 1) & 3))) << 4));
                }
                uint32_t bf[4][4];
                #pragma unroll
                for (int g = 0; g < 4; g++) {
                    int kr = s * 16 + mlane;
                    int chn = wn * 8 + g * 2 + lhi;
                    ldsm_x4_t(bf[g], Bbase + (kr << 9) + (((chn ^ (kr & 7))) << 4));
                }
                #pragma unroll
                for (int f = 0; f < 4; f++)
                    #pragma unroll
                    for (int g = 0; g < 4; g++) {
                        mma16816(acc[f][g*2+0], af[f], bf[g][0], bf[g][1]);
                        mma16816(acc[f][g*2+1], af[f], bf[g][2], bf[g][3]);
                    }
            }
        }
        if (c + 1 < nk) {
            char* As = smh + ((c + 1) & 1) * ASZ;
            char* Bs = smh + 2 * ASZ + ((c + 1) & 1) * BSZ;
            #pragma unroll
            for (int j = 0; j < 4; j++) *(uint2*)(As + aoff[j]) = pa[j];
            #pragma unroll
            for (int j = 0; j < 8; j++) {
                uint2 w; w.x = pack2(pb[j].x, pb[j].y); w.y = pack2(pb[j].z, pb[j].w);
                *(uint2*)(Bs + boff[j]) = w;
            }
        }
        __syncthreads();
    }

    const int r = lane >> 2, cl = lane & 3;
    #pragma unroll
    for (int f = 0; f < 4; f++) {
        #pragma unroll
        for (int h = 0; h < 2; h++) {
            size_t gr = (size_t)(mt * TBM + wm * 64 + f * 16 + r + h * 8);
            const float* rrow = RESID ? (resid + gr * ldc) : nullptr;
            #pragma unroll
            for (int nf = 0; nf < 8; nf++) {
                int gc = nt * TBN + wn * 64 + nf * 8 + cl * 2;
                float v0 = acc[f][nf][h * 2 + 0];
                float v1 = acc[f][nf][h * 2 + 1];
                if (SILU) {
                    v0 = v0 / (1.f + __expf(-v0));
                    v1 = v1 / (1.f + __expf(-v1));
                }
                if (RESID) { v0 += rrow[gc]; v1 += rrow[gc + 1]; }
                if (OUTH) {
                    __half2 o = __floats2half2_rn(v0, v1);
                    *(__half2*)((__half*)Cv + gr * ldc + gc) = o;
                } else {
                    float2 o; o.x = v0; o.y = v1;
                    *(float2*)((float*)Cv + gr * ldc + gc) = o;
                }
            }
        }
    }
}

// fused QKV: nt 0..7 -> Wq (fp32 out), 8..9 -> Wk (fp32 out), 10..11 -> Wv (fp16 out)
__global__ void __launch_bounds__(256, 1) k_gemm_qkv(const float* __restrict__ Wq,
                                                     const float* __restrict__ Wk,
                                                     const float* __restrict__ Wv) {
    int nt = blockIdx.x, mt = blockIdx.y;
    if (nt < 8)
        tgemm<false,false,false,false>(g_hh, Wq, g_q, DD, DD, HH*DKK, HH*DKK, nt, mt,
                                       nullptr, nullptr);
    else if (nt < 10)
        tgemm<false,false,false,false>(g_hh, Wk, g_k, DD, DD, GG*DKK, GG*DKK, nt - 8, mt,
                                       nullptr, nullptr);
    else
        tgemm<false,false,false,true>(g_hh, Wv, g_vh, DD, DD, GG*DVV, GG*DVV, nt - 10, mt,
                                      nullptr, nullptr);
}
__global__ void __launch_bounds__(256, 1) k_gemm_o(const float* __restrict__ Wo,
                                                   const float* __restrict__ xin) {
    tgemm<false,true,false,false>(g_attnh, Wo, g_x1, HH*DVV, HH*DVV, DD, DD,
                                  blockIdx.x, blockIdx.y, xin, nullptr);
}
__global__ void __launch_bounds__(256, 1) k_moe1(const float* __restrict__ W1) {
    int e = g_tile_e[blockIdx.y];
    if (e < 0) return;
    tgemm<true,false,true,true>(g_th, W1 + (long long)e * DD * FF, g_midh, DD, DD, FF, FF,
                                blockIdx.x, blockIdx.y, nullptr, g_row_token);
}
__global__ void __launch_bounds__(256, 1) k_moe2(const float* __restrict__ W2) {
    int e = g_tile_e[blockIdx.y];
    if (e < 0) return;
    tgemm<false,false,false,false>(g_midh, W2 + (long long)e * FF * DD, g_mid2,
                                   FF, FF, DD, DD, blockIdx.x, blockIdx.y,
                                   nullptr, nullptr);
}

// ---------------- RoPE (fp32 in, fp16 out) ----------------
__device__ __forceinline__ void rope_core(const float* __restrict__ in,
                                          __half* __restrict__ outh, int heads) {
    int idx = blockIdx.x;
    int tokenpos = (idx / heads) % SS;
    const float* row = in + (size_t)idx * DKK;
    __half* orow = outh + (size_t)idx * DKK;
    int i = threadIdx.x;                  // 0..63
    float ex = (float)i * (1.0f / 64.0f);
    float invf = expf(-ex * 9.210340371976184f);
    float ang = (float)tokenpos * invf;
    float c, s;
    sincosf(ang, &s, &c);
    float x1 = row[i], x2 = row[i + 64];
    orow[i]      = __float2half(x1 * c - x2 * s);
    orow[i + 64] = __float2half(x1 * s + x2 * c);
}
__global__ void k_rope_q() { rope_core(g_q, g_qh, HH); }
__global__ void k_rope_k() { rope_core(g_k, g_kh, GG); }

// ---------------- Flash attention, fp16 in/out ----------------
#define QROW 272
#define PLD 68
#define PSHROW 144
#define OFF_KS (64*QROW)
#define OFF_VS (2*64*QROW)
#define OFF_PS (3*64*QROW)
#define OFF_PSH (OFF_PS + 64*PLD*4)
#define OFF_MISC (OFF_PSH + 64*PSHROW)
#define ATTN_SMEM (OFF_MISC + 3*64*4)   // 79616

__global__ void __launch_bounds__(256) k_attn() {
    extern __shared__ char sma[];
    const uint32_t su = smem_to_u32(sma);
    float* ps   = (float*)(sma + OFF_PS);
    float* mrow = (float*)(sma + OFF_MISC);
    float* lrow = mrow + 64;
    float* arow = lrow + 64;
    const int qt = 15 - blockIdx.x;
    const int hh = blockIdx.y, b = blockIdx.z;
    const int g = hh >> 2;
    const int tid = threadIdx.x;
    const int lane = tid & 31, warp = tid >> 5;
    const int r = lane >> 2, cl = lane & 3;
    const int mlane = ((lane >> 3) & 1) * 8 + (lane & 7);
    const int lhi = lane >> 4;
    const int swm = warp >> 1, swn = warp & 1;
    const int m0 = swm * 16;

    // load Q tile once (fp16 -> fp16 smem, uint4 16B)
    for (int id = tid; id < 64 * 16; id += 256) {
        int m = id >> 4, c8 = (id & 15) << 3;
        const __half* src = g_qh + (((size_t)((b * SS + qt * 64 + m) * HH + hh)) << 7) + c8;
        *(uint4*)(sma + m * QROW + c8 * 2) = *(const uint4*)src;
    }
    if (tid < 64) { mrow[tid] = -1e30f; lrow[tid] = 0.f; }

    float oacc[8][4];
    #pragma unroll
    for (int nf = 0; nf < 8; nf++)
        #pragma unroll
        for (int i = 0; i < 4; i++) oacc[nf][i] = 0.f;

    const float scale = 0.08838834764831845f;

    for (int kt = 0; kt <= qt; kt++) {
        __syncthreads();
        for (int id = tid; id < 64 * 16; id += 256) {
            int n = id >> 4, c8 = (id & 15) << 3;
            size_t gidx = (((size_t)((b * SS + kt * 64 + n) * GG + g)) << 7) + c8;
            *(uint4*)(sma + OFF_KS + n * QROW + c8 * 2) = *(const uint4*)(g_kh + gidx);
            *(uint4*)(sma + OFF_VS + n * QROW + c8 * 2) = *(const uint4*)(g_vh + gidx);
        }
        __syncthreads();

        // S = Q K^T (warp 16x32, 8 k16 steps)
        float sacc[4][4];
        #pragma unroll
        for (int t = 0; t < 4; t++)
            #pragma unroll
            for (int i = 0; i < 4; i++) sacc[t][i] = 0.f;
        const int sn0 = swn * 32;
        const uint32_t qb = su + (m0 + mlane) * QROW + lhi * 16;
        const uint32_t kb0 = su + OFF_KS + (sn0 + mlane) * QROW + lhi * 16;
        const uint32_t kb1 = kb0 + 16 * QROW;
        #pragma unroll
        for (int kc = 0; kc < 8; kc++) {
            uint32_t af[4], bk0[4], bk1[4];
            ldsm_x4(af, qb + kc * 32);
            ldsm_x4(bk0, kb0 + kc * 32);
            ldsm_x4(bk1, kb1 + kc * 32);
            mma16816(sacc[0], af, bk0[0], bk0[2]);
            mma16816(sacc[1], af, bk0[1], bk0[3]);
            mma16816(sacc[2], af, bk1[0], bk1[2]);
            mma16816(sacc[3], af, bk1[1], bk1[3]);
        }
        {
            int gm0 = qt * 64 + m0 + r;
            #pragma unroll
            for (int t = 0; t < 4; t++) {
                int gn = kt * 64 + sn0 + t * 8 + 2 * cl;
                float v0 = sacc[t][0] * scale; if (gn     > gm0)     v0 = -1e30f;
                float v1 = sacc[t][1] * scale; if (gn + 1 > gm0)     v1 = -1e30f;
                float v2 = sacc[t][2] * scale; if (gn     > gm0 + 8) v2 = -1e30f;
                float v3 = sacc[t][3] * scale; if (gn + 1 > gm0 + 8) v3 = -1e30f;
                float2 p01; p01.x = v0; p01.y = v1;
                float2 p23; p23.x = v2; p23.y = v3;
                *(float2*)&ps[(m0 + r) * PLD + sn0 + t * 8 + 2 * cl] = p01;
                *(float2*)&ps[(m0 + r + 8) * PLD + sn0 + t * 8 + 2 * cl] = p23;
            }
        }
        __syncthreads();
        // online softmax: 4 threads/row, quad shfl; write P fp16
        {
            int row = tid >> 2, part = tid & 3;
            float mx = mrow[row];
            const float* pr = ps + row * PLD + part * 16;
            float tmax = -1e30f;
            #pragma unroll
            for (int n = 0; n < 16; n++) tmax = fmaxf(tmax, pr[n]);
            tmax = fmaxf(tmax, __shfl_xor_sync(0xffffffffu, tmax, 1));
            tmax = fmaxf(tmax, __shfl_xor_sync(0xffffffffu, tmax, 2));
            float nm = fmaxf(mx, tmax);
            float al = __expf(mx - nm);
            float sum = 0.f;
            __half* ph = (__half*)(sma + OFF_PSH + row * PSHROW) + part * 16;
            #pragma unroll
            for (int n = 0; n < 16; n += 2) {
                float p0 = __expf(pr[n] - nm);
                float p1 = __expf(pr[n + 1] - nm);
                sum += p0 + p1;
                *(__half2*)(ph + n) = __floats2half2_rn(p0, p1);
            }
            sum += __shfl_xor_sync(0xffffffffu, sum, 1);
            sum += __shfl_xor_sync(0xffffffffu, sum, 2);
            if (part == 0) {
                lrow[row] = lrow[row] * al + sum;
                mrow[row] = nm;
                arow[row] = al;
            }
        }
        __syncthreads();
        // PV (warp 16x64, 4 k16 steps)
        {
            float al0 = arow[m0 + r], al1 = arow[m0 + r + 8];
            #pragma unroll
            for (int nf = 0; nf < 8; nf++) {
                oacc[nf][0] *= al0; oacc[nf][1] *= al0;
                oacc[nf][2] *= al1; oacc[nf][3] *= al1;
            }
            const int dn0 = swn * 64;
            const uint32_t pb = su + OFF_PSH + (m0 + mlane) * PSHROW + lhi * 16;
            const uint32_t vb = su + OFF_VS + mlane * QROW + dn0 * 2 + lhi * 16;
            #pragma unroll
            for (int kc = 0; kc < 4; kc++) {
                uint32_t af[4];
                ldsm_x4(af, pb + kc * 32);
                #pragma unroll
                for (int g2 = 0; g2 < 4; g2++) {
                    uint32_t bf[4];
                    ldsm_x4_t(bf, vb + kc * 16 * QROW + g2 * 32);
                    mma16816(oacc[g2*2+0], af, bf[0], bf[1]);
                    mma16816(oacc[g2*2+1], af, bf[2], bf[3]);
                }
            }
        }
    }
    // write out (fp16)
    {
        float inv0 = 1.f / lrow[m0 + r];
        float inv1 = 1.f / lrow[m0 + r + 8];
        const int dn0 = swn * 64;
        __half* dst0 = g_attnh + (((size_t)((b * SS + qt * 64 + m0 + r) * HH + hh)) << 7);
        __half* dst1 = g_attnh + (((size_t)((b * SS + qt * 64 + m0 + r + 8) * HH + hh)) << 7);
        #pragma unroll
        for (int nf = 0; nf < 8; nf++) {
            int d = dn0 + nf * 8 + 2 * cl;
            *(__half2*)(dst0 + d) = __floats2half2_rn(oacc[nf][0] * inv0, oacc[nf][1] * inv0);
            *(__half2*)(dst1 + d) = __floats2half2_rn(oacc[nf][2] * inv1, oacc[nf][3] * inv1);
        }
    }
}

// ---------------- router + MoE bookkeeping ----------------
__global__ void k_init() {
    int i = blockIdx.x * 256 + threadIdx.x;
    if (i < NE) g_count[i] = 0;
    if (i < MAXROWS) g_row_token[i] = 0;
}

__global__ void __launch_bounds__(128) k_router(const float* __restrict__ Wr) {
    int tok = blockIdx.x;
    const float* tr = g_t + (size_t)tok * DD;
    float acc[8] = {0,0,0,0,0,0,0,0};
    for (int d = threadIdx.x; d < DD; d += 128) {
        float tv = tr[d];
        const float4* wr = (const float4*)(Wr + (size_t)d * 8);
        float4 w0 = wr[0], w1 = wr[1];
        acc[0] = fmaf(tv, w0.x, acc[0]); acc[1] = fmaf(tv, w0.y, acc[1]);
        acc[2] = fmaf(tv, w0.z, acc[2]); acc[3] = fmaf(tv, w0.w, acc[3]);
        acc[4] = fmaf(tv, w1.x, acc[4]); acc[5] = fmaf(tv, w1.y, acc[5]);
        acc[6] = fmaf(tv, w1.z, acc[6]); acc[7] = fmaf(tv, w1.w, acc[7]);
    }
    __shared__ float red[4][8];
    #pragma unroll
    for (int e = 0; e < 8; e++) {
        float v = warp_sum(acc[e]);
        if ((threadIdx.x & 31) == 0) red[threadIdx.x >> 5][e] = v;
    }
    __syncthreads();
    if (threadIdx.x == 0) {
        float lg[8];
        #pragma unroll
        for (int e = 0; e < 8; e++) lg[e] = red[0][e] + red[1][e] + red[2][e] + red[3][e];
        int i0 = 0;
        for (int e = 1; e < 8; e++) if (lg[e] > lg[i0]) i0 = e;
        int i1 = -1;
        for (int e = 0; e < 8; e++) {
            if (e == i0) continue;
            if (i1 < 0 || lg[e] > lg[i1]) i1 = e;
        }
        float e1v = __expf(lg[i1] - lg[i0]);
        float s = 1.f + e1v;
        float gg0 = 1.f / s, gg1 = e1v / s;
        int p0 = atomicAdd(&g_count[i0], 1);
        int p1 = atomicAdd(&g_count[i1], 1);
        g_pair_e[tok*2]   = i0; g_pair_pos[tok*2]   = p0; g_pair_gate[tok*2]   = gg0;
        g_pair_e[tok*2+1] = i1; g_pair_pos[tok*2+1] = p1; g_pair_gate[tok*2+1] = gg1;
    }
}

__global__ void k_finalize() {
    if (threadIdx.x != 0 || blockIdx.x != 0) return;
    int off = 0;
    for (int e = 0; e < NE; e++) {
        g_offset[e] = off;
        int pt = (g_count[e] + 127) / 128;
        for (int ti = 0; ti < pt; ti++) g_tile_e[off / 128 + ti] = e;
        off += pt * 128;
    }
    for (int i = off / 128; i < MAXTILES; i++) g_tile_e[i] = -1;
}

__global__ void k_rows_place() {
    int p = blockIdx.x * 256 + threadIdx.x;
    if (p < TT * KTOP) {
        int e = g_pair_e[p];
        int row = g_offset[e] + g_pair_pos[p];
        g_row_token[row] = p >> 1;
        g_row_of_pair[p] = row;
    }
}

__global__ void __launch_bounds__(256) k_combine(float* __restrict__ out) {
    int tok = blockIdx.x;
    int r0 = g_row_of_pair[tok*2], r1 = g_row_of_pair[tok*2+1];
    float gg0 = g_pair_gate[tok*2], gg1 = g_pair_gate[tok*2+1];
    const float4* a  = (const float4*)(g_x1  + (size_t)tok * DD);
    const float4* m0 = (const float4*)(g_mid2 + (size_t)r0 * DD);
    const float4* m1 = (const float4*)(g_mid2 + (size_t)r1 * DD);
    float4* o4 = (float4*)(out + (size_t)tok * DD);
    for (int i = threadIdx.x; i < DD / 4; i += 256) {
        float4 av = a[i], v0 = m0[i], v1 = m1[i], r;
        r.x = av.x + gg0 * v0.x + gg1 * v1.x;
        r.y = av.y + gg0 * v0.y + gg1 * v1.y;
        r.z = av.z + gg0 * v0.z + gg1 * v1.z;
        r.w = av.w + gg0 * v0.w + gg1 * v1.w;
        o4[i] = r;
    }
}

// ---------------- launch ----------------
extern "C" void kernel_launch(void* const* d_in, const int* in_sizes, int n_in,
                              void* d_out, int out_size) {
    const float* x    = (const float*)d_in[0];
    const float* ln1w = (const float*)d_in[1];
    const float* Wq   = (const float*)d_in[2];
    const float* Wk   = (const float*)d_in[3];
    const float* Wv   = (const float*)d_in[4];
    const float* Wo   = (const float*)d_in[5];
    const float* ln2w = (const float*)d_in[6];
    const float* Wr   = (const float*)d_in[7];
    const float* W1   = (const float*)d_in[8];
    const float* W2   = (const float*)d_in[9];
    float* out = (float*)d_out;
    (void)in_sizes; (void)n_in; (void)out_size;

    cudaFuncSetAttribute(k_gemm_qkv, cudaFuncAttributeMaxDynamicSharedMemorySize, TG_SMEM);
    cudaFuncSetAttribute(k_gemm_o,   cudaFuncAttributeMaxDynamicSharedMemorySize, TG_SMEM);
    cudaFuncSetAttribute(k_moe1,     cudaFuncAttributeMaxDynamicSharedMemorySize, TG_SMEM);
    cudaFuncSetAttribute(k_moe2,     cudaFuncAttributeMaxDynamicSharedMemorySize, TG_SMEM);
    cudaFuncSetAttribute(k_attn,     cudaFuncAttributeMaxDynamicSharedMemorySize, ATTN_SMEM);

    k_rms1<<<TT, 256>>>(x, ln1w);
    k_gemm_qkv<<<dim3(12, TT/TBM), 256, TG_SMEM>>>(Wq, Wk, Wv);   // 192 CTAs
    k_rope_q<<<TT * HH, 64>>>();
    k_rope_k<<<TT * GG, 64>>>();
    k_attn<<<dim3(16, 16, 2), 256, ATTN_SMEM>>>();
    k_gemm_o<<<dim3(DD/TBN, TT/TBM), 256, TG_SMEM>>>(Wo, x);      // 128 CTAs
    k_rms2<<<TT, 256>>>(ln2w);
    k_init<<<(MAXROWS + 255) / 256, 256>>>();
    k_router<<<TT, 128>>>(Wr);
    k_finalize<<<1, 1>>>();
    k_rows_place<<<(TT * KTOP + 255) / 256, 256>>>();
    k_moe1<<<dim3(FF/TBN, MAXTILES), 256, TG_SMEM>>>(W1);         // (16,40)
    k_moe2<<<dim3(DD/TBN, MAXTILES), 256, TG_SMEM>>>(W2);         // (8,40)
    k_combine<<<TT, 256>>>(out);
}